// round 10
// baseline (speedup 1.0000x reference)
#include <cuda_runtime.h>
#include <cstddef>
#include <cstdint>

#define NPTS   640000
#define NCAM   6
#define HH     512
#define WW     1408
#define NPIX   (HH * WW)
#define NCH    17
#define VOXS   0.4f
#define NX     200
#define NSL    3200               // scanlines; point idx = ix*NSL + sl
#define SEGW   128
#define NSEG   11                 // 11*128 == WW
#define BROWS  2
#define BTHR   256
#define LISTCAP 96
#define RECCAP 48
#define GB     4                  // scanlines staged per barrier pair
#define PSTR   20                 // packed record: 17 op-premult feats + op + 2 pad

typedef unsigned long long u64;

// Scratch: fast path = packed feats; fallback = logit image.
__device__ __align__(16) float g_img[(size_t)NCAM * NPIX * NCH];
__device__ double g_num[NCAM];
__device__ double g_den[NCAM];
__device__ int    g_flag;
__device__ float  g_rec0[NCAM][NSL][4];   // u0, inv_du, v, iz
__device__ float  g_rec1[NCAM][NSL][4];   // j00, j12, cS, c_yz
__device__ short  g_rv[NCAM][NSL];        // rint(v) or 32000

__device__ __forceinline__ void red_add_f32(float* addr, float a) {
    asm volatile("red.global.add.f32 [%0], %1;" :: "l"(addr), "f"(a) : "memory");
}
#define FMA2(d, a, b, c) \
    asm("fma.rn.f32x2 %0, %1, %2, %3;" : "=l"(d) : "l"(a), "l"(b), "l"(c))

__device__ __forceinline__ float ex2f(float x) {
    float r;
    asm("ex2.approx.ftz.f32 %0, %1;" : "=f"(r) : "f"(x));
    return r;
}

// ---------------------------------------------------------------------------
// 1) prep1: matrix structure check, zero accumulators
// ---------------------------------------------------------------------------
__global__ void prep1_kernel(const float* __restrict__ vm) {
    if (threadIdx.x == 0) {
        int ok = 1;
        for (int c = 0; c < NCAM; c++)
            if (vm[c * 16 + 4] != 0.0f || vm[c * 16 + 8] != 0.0f) ok = 0;
        g_flag = ok;
    }
    if (threadIdx.x < NCAM) { g_num[threadIdx.x] = 0.0; g_den[threadIdx.x] = 0.0; }
}

// ---------------------------------------------------------------------------
// 2) prep2: per (cam, scanline) records + |du| guard for 2-candidate loop
// ---------------------------------------------------------------------------
__global__ void __launch_bounds__(256)
prep2_kernel(const float* __restrict__ xyz, const float* __restrict__ vm,
             const float* __restrict__ Ks) {
    int sl = blockIdx.x * 256 + threadIdx.x;
    if (sl >= NSL) return;
    float X0 = xyz[3 * sl], Y0 = xyz[3 * sl + 1], Z0 = xyz[3 * sl + 2];
    float Xe = xyz[3 * ((size_t)(NX - 1) * NSL + sl)];
    for (int cam = 0; cam < NCAM; cam++) {
        const float* M = vm + cam * 16;
        const float* K = Ks + cam * 9;
        float m0  = M[0];
        float cyz = fmaf(M[1], Y0, fmaf(M[2], Z0, M[3]));
        float p1  = fmaf(M[4], X0, fmaf(M[5], Y0, fmaf(M[6],  Z0, M[7])));
        float p2  = fmaf(M[8], X0, fmaf(M[9], Y0, fmaf(M[10], Z0, M[11])));
        float fx = K[0], cx = K[2], fy = K[4], cy = K[5];
        float zc = fmaxf(p2, 0.001f), iz = 1.0f / zc;
        float v   = fy * p1 * iz + cy;
        float j00 = fx * iz, j11 = fy * iz;
        float j12 = -fy * p1 * iz * iz;
        float cS  = VOXS * VOXS * (j11 * j11 + j12 * j12) + 0.3f;
        float p00 = fmaf(m0, X0, cyz), p0e = fmaf(m0, Xe, cyz);
        float u0  = fx * p00 * iz + cx;
        float ue  = fx * p0e * iz + cx;
        float du  = (ue - u0) * (1.0f / (float)(NX - 1));
        bool  val = (p2 > 0.1f);
        float rvf = rintf(v);
        bool  rel = val && (rvf >= -1.5f) && (rvf <= (float)HH + 0.5f);
        // need hw = 0.55 + 1.65*|idu| < 1.0  =>  |du| > 3.71 for the
        // 2-candidate inner loop to be exhaustive
        if (rel && fabsf(du) < 3.71f) atomicAnd(&g_flag, 0);
        float idu = (du != 0.0f) ? 1.0f / du : 0.0f;
        g_rec0[cam][sl][0] = u0;  g_rec0[cam][sl][1] = idu;
        g_rec0[cam][sl][2] = v;   g_rec0[cam][sl][3] = iz;
        g_rec1[cam][sl][0] = j00; g_rec1[cam][sl][1] = j12;
        g_rec1[cam][sl][2] = cS;  g_rec1[cam][sl][3] = cyz;
        g_rv[cam][sl] = rel ? (short)(int)rvf : (short)32000;
    }
}

// ---------------------------------------------------------------------------
// 3) verrepack: grid verification + coalesced repack of op-premultiplied feats
// ---------------------------------------------------------------------------
__global__ void __launch_bounds__(256)
verrepack_kernel(const float* __restrict__ xyz, const float* __restrict__ feats,
                 const float* __restrict__ opac) {
    __shared__ float sf[256 * NCH];
    const int blk = blockIdx.x;
    const int tid = threadIdx.x;
    const int i   = blk * 256 + tid;

    // structure verification: Y,Z scanline-const; X shared & linear in ix
    int ix = i / NSL, sl = i - ix * NSL;
    float X = xyz[3 * i], Y = xyz[3 * i + 1], Z = xyz[3 * i + 2];
    float X0 = xyz[0];
    float Xe = xyz[3 * (size_t)((NX - 1) * NSL)];
    float dX = (Xe - X0) * (1.0f / (float)(NX - 1));
    bool ok = (Y == xyz[3 * sl + 1]) && (Z == xyz[3 * sl + 2]) &&
              (X == xyz[3 * (size_t)(ix * NSL)]);
    float Xlin = fmaf((float)ix, dX, X0);
    ok = ok && (fabsf(X - Xlin) <= fmaf(0.01f, fabsf(dX), 1e-5f));
    if (!ok) atomicAnd(&g_flag, 0);

    // repack (coalesced read via smem), feats pre-multiplied by opacity
    const float* src = feats + (size_t)blk * 256 * NCH;
    for (int j = tid; j < 256 * NCH / 4; j += 256) {
        float4 vv = reinterpret_cast<const float4*>(src)[j];
        sf[4 * j] = vv.x; sf[4 * j + 1] = vv.y; sf[4 * j + 2] = vv.z; sf[4 * j + 3] = vv.w;
    }
    __syncthreads();
    float op = opac[i];
    float r[PSTR];
#pragma unroll
    for (int c = 0; c < NCH; c++) r[c] = op * sf[tid * NCH + c];
    r[17] = op; r[18] = 0.f; r[19] = 0.f;
    float4* o = reinterpret_cast<float4*>(g_img + (size_t)i * PSTR);
#pragma unroll
    for (int q = 0; q < 5; q++)
        o[q] = make_float4(r[4 * q], r[4 * q + 1], r[4 * q + 2], r[4 * q + 3]);
}

// ---------------------------------------------------------------------------
// 4) FUSED GATHER: block = 2 rows x 128 px. Batched staging: GB scanlines'
//    records+headers per barrier pair. Uniform 2-candidate hit loop, f32x2 acc.
// ---------------------------------------------------------------------------
__global__ void __launch_bounds__(BTHR)
fused_kernel(const float* __restrict__ xyz, const float* __restrict__ vm,
             const float* __restrict__ Ks, const int* __restrict__ gt,
             const float* __restrict__ cw) {
    if (!g_flag) return;
    const int bix = blockIdx.x;
    const int cam = bix / ((HH / BROWS) * NSEG);
    const int rem = bix - cam * ((HH / BROWS) * NSEG);
    const int rp  = rem / NSEG;
    const int seg = rem - rp * NSEG;
    const int r0  = rp * BROWS;
    const int tid = threadIdx.x;
    const int px  = seg * SEGW + (tid & (SEGW - 1));
    const int rowoff = tid >> 7;                 // 0 or 1
    const int row = r0 + rowoff;

    __shared__ float  sX[NX];
    __shared__ int    s_n;
    __shared__ int    Lsl[LISTCAP];
    __shared__ int2   Lwin[LISTCAP];             // ilo, ihi
    __shared__ float4 LV[LISTCAP];               // u0, idu, v, hw  (hot)
    __shared__ float4 LSa[LISTCAP];              // Fiz, iz, cS, a0 (staging)
    __shared__ float2 LSb[LISTCAP];              // sj12, cyz       (staging)
    __shared__ float4 sH[2][GB * RECCAP];        // per row: u, A, B, C
    __shared__ float4 sF[GB * RECCAP * 5];       // premult feats
    __shared__ float  wn[BTHR / 32], wd[BTHR / 32];

    for (int ix = tid; ix < NX; ix += BTHR)
        sX[ix] = xyz[3 * (size_t)(ix * NSL)];
    if (tid == 0) s_n = 0;
    __syncthreads();

    // scanlines whose stamps touch rows [r0, r0+1]: rv in [r0-1, r0+2]
    for (int sl = tid; sl < NSL; sl += BTHR) {
        int d = r0 - (int)g_rv[cam][sl];
        if (d >= -2 && d <= 1) {
            int k = atomicAdd(&s_n, 1);
            if (k < LISTCAP) Lsl[k] = sl;
        }
    }
    __syncthreads();
    const int  nl  = s_n;
    const bool big = (nl > LISTCAP);

    const float fx = Ks[cam * 9 + 0], cx = Ks[cam * 9 + 2];
    const float m0 = vm[cam * 16 + 0];
    const float s2 = VOXS * VOXS;
    const float K2 = -0.72134752f;               // -0.5 * log2(e)
    const float px0f = (float)(seg * SEGW);
    const float px1f = px0f + (float)(SEGW - 1);

    if (!big) {
        for (int k = tid; k < nl; k += BTHR) {
            int sl = Lsl[k];
            float4 a = *reinterpret_cast<const float4*>(g_rec0[cam][sl]);
            float4 b = *reinterpret_cast<const float4*>(g_rec1[cam][sl]);
            float hw = fmaf(fabsf(a.y), 1.65f, 0.55f);
            LV[k]  = make_float4(a.x, a.y, a.z, hw);
            LSa[k] = make_float4(fx * a.w, a.w, b.z, fmaf(s2 * b.x, b.x, 0.3f));
            LSb[k] = make_float2(s2 * b.y, b.w);
            float t0 = (px0f - a.x) * a.y;
            float t1 = (px1f - a.x) * a.y;
            int ilo = max(0, __float2int_ru(fminf(t0, t1) - hw));
            int ihi = min(NX - 1, __float2int_rd(fmaxf(t0, t1) + hw));
            Lwin[k] = make_int2(ilo, ihi);
        }
    }
    __syncthreads();

    u64 acc[8];
    float acc16 = 0.f;
#pragma unroll
    for (int q = 0; q < 8; q++) acc[q] = 0ull;

    const float fpx  = (float)px;
    const float rowf = (float)row;
    const float* pack = g_img;
    const float4* pack4 = reinterpret_cast<const float4*>(g_img);

    if (!big) {
        for (int kb = 0; kb < nl; kb += GB) {
            const int ne = min(GB, nl - kb);
            __syncthreads();                      // protect sF/sH reuse

            // ---- stage feats for up to GB scanlines (latencies overlap) ----
            for (int j = 0; j < ne; j++) {
                const int k = kb + j;
                const int2 win = Lwin[k];
                const int cnt = win.y - win.x + 1;
                if (cnt <= 0 || cnt > RECCAP) continue;
                const int sl = Lsl[k];
                const int nq = cnt * 5;
                const int base4 = (win.x * NSL + sl) * 5;   // 32-bit
                for (int q = tid; q < nq; q += BTHR) {
                    int rr = q / 5, w = q - rr * 5;
                    sF[j * (RECCAP * 5) + q] = pack4[base4 + rr * (NSL * 5) + w];
                }
            }
            // ---- headers: 64-thread group per scanline ----
            {
                const int j = tid >> 6;           // 0..3
                const int local = tid & 63;
                if (j < ne) {
                    const int k = kb + j;
                    const int2 win = Lwin[k];
                    const int cnt = win.y - win.x + 1;
                    if (local < cnt && cnt <= RECCAP) {
                        float4 sa = LSa[k]; float2 sb = LSb[k];
                        float v  = LV[k].z;
                        float X  = sX[win.x + local];
                        float u  = fmaf(sa.x, fmaf(m0, X, sb.y), cx);
                        float j02 = (cx - u) * sa.y;
                        float av  = fmaf(s2 * j02, j02, sa.w);
                        float bv  = sb.x * j02;
                        float det = fmaf(av, sa.z, -bv * bv);
                        float idet = 1.0f / det;
                        float A   = K2 * sa.z * idet;
                        float B2  = -2.0f * K2 * bv * idet;
                        float Cc  = K2 * av * idet;
                        float dy0 = (float)r0 - v;
                        float dy1 = dy0 + 1.0f;
                        sH[0][j * RECCAP + local] =
                            make_float4(u, A, B2 * dy0, Cc * dy0 * dy0);
                        sH[1][j * RECCAP + local] =
                            make_float4(u, A, B2 * dy1, Cc * dy1 * dy1);
                    }
                }
            }
            __syncthreads();

            // ---- compute the ne scanlines from SMEM (no barriers between) ----
            for (int j = 0; j < ne; j++) {
                const int k = kb + j;
                const int2 win = Lwin[k];
                const int cnt = win.y - win.x + 1;
                if (cnt <= 0) continue;
                const float4 wv4 = LV[k];

                if (cnt <= RECCAP) {
                    if (fabsf(rowf - rintf(wv4.z)) <= 1.0f) {    // rel
                        float t = (fpx - wv4.x) * wv4.y;
                        int clo = max(win.x, __float2int_ru(t - wv4.w));
                        int chi = min(win.y, __float2int_rd(t + wv4.w));
                        const float4* Hrow = sH[rowoff] + j * RECCAP;
                        const float4* Fj   = sF + j * (RECCAP * 5);
#pragma unroll
                        for (int q = 0; q < 2; q++) {            // uniform trip
                            int ix = clo + q;
                            bool act = (ix <= chi);
                            int jj = act ? (ix - win.x) : 0;
                            float4 h = Hrow[jj];
                            float dd = rintf(h.x) - fpx;
                            if (act && fabsf(dd) < 1.5f) {
                                float ddx = fpx - h.x;
                                float e = fmaf(fmaf(h.y, ddx, h.z), ddx, h.w);
                                float w = ex2f(e);
                                u64 w2;
                                asm("mov.b64 %0, {%1, %1};" : "=l"(w2) : "f"(w));
                                const ulonglong2* rf =
                                    reinterpret_cast<const ulonglong2*>(&Fj[jj * 5]);
                                ulonglong2 p0 = rf[0], p1 = rf[1];
                                FMA2(acc[0], w2, p0.x, acc[0]);
                                FMA2(acc[1], w2, p0.y, acc[1]);
                                FMA2(acc[2], w2, p1.x, acc[2]);
                                FMA2(acc[3], w2, p1.y, acc[3]);
                                ulonglong2 p2 = rf[2], p3 = rf[3];
                                FMA2(acc[4], w2, p2.x, acc[4]);
                                FMA2(acc[5], w2, p2.y, acc[5]);
                                FMA2(acc[6], w2, p3.x, acc[6]);
                                FMA2(acc[7], w2, p3.y, acc[7]);
                                float4 f4 = Fj[jj * 5 + 4];
                                acc16 = fmaf(w, f4.x, acc16);
                            }
                        }
                    }
                } else {
                    // defensive overflow: direct per-thread path, exact math
                    if (fabsf(rowf - rintf(wv4.z)) > 1.0f) continue;
                    const float4 sa = LSa[k]; const float2 sb = LSb[k];
                    const int sl = Lsl[k];
                    const float ddy = rowf - wv4.z;
                    float t = (fpx - wv4.x) * wv4.y;
                    int clo = max(win.x, __float2int_ru(t - wv4.w));
                    int chi = min(win.y, __float2int_rd(t + wv4.w));
                    for (int ix = clo; ix <= chi; ix++) {
                        float X  = sX[ix];
                        float u  = fmaf(sa.x, fmaf(m0, X, sb.y), cx);
                        float dd = rintf(u) - fpx;
                        if (fabsf(dd) > 1.5f) continue;
                        float ddx = fpx - u;
                        float j02 = (cx - u) * sa.y;
                        float av  = fmaf(s2 * j02, j02, sa.w);
                        float bv  = sb.x * j02;
                        float det = fmaf(av, sa.z, -bv * bv);
                        float e = K2 / det *
                            (fmaf(fmaf(sa.z, ddx, -2.0f * bv * ddy), ddx,
                                  av * ddy * ddy));
                        float w = ex2f(e);
                        u64 w2;
                        asm("mov.b64 %0, {%1, %1};" : "=l"(w2) : "f"(w));
                        const ulonglong2* rf = reinterpret_cast<const ulonglong2*>(
                            pack + (size_t)(ix * NSL + sl) * PSTR);
                        ulonglong2 p0 = rf[0], p1 = rf[1], p2 = rf[2], p3 = rf[3];
                        FMA2(acc[0], w2, p0.x, acc[0]);
                        FMA2(acc[1], w2, p0.y, acc[1]);
                        FMA2(acc[2], w2, p1.x, acc[2]);
                        FMA2(acc[3], w2, p1.y, acc[3]);
                        FMA2(acc[4], w2, p2.x, acc[4]);
                        FMA2(acc[5], w2, p2.y, acc[5]);
                        FMA2(acc[6], w2, p3.x, acc[6]);
                        FMA2(acc[7], w2, p3.y, acc[7]);
                        acc16 = fmaf(w, pack[(size_t)(ix * NSL + sl) * PSTR + 16],
                                     acc16);
                    }
                }
            }
        }
    } else {
        // never-expected overflow: full scanline scan, direct loads
        for (int sl = 0; sl < NSL; sl++) {
            int d = r0 - (int)g_rv[cam][sl];
            if (d < -2 || d > 1) continue;
            float4 a = *reinterpret_cast<const float4*>(g_rec0[cam][sl]);
            float4 b = *reinterpret_cast<const float4*>(g_rec1[cam][sl]);
            float u0 = a.x, idu = a.y, v = a.z, iz = a.w;
            if (fabsf(rowf - rintf(v)) > 1.0f) continue;
            float ddy = rowf - v;
            float Fiz = fx * iz, cS = b.z;
            float a0 = fmaf(s2 * b.x, b.x, 0.3f);
            float sj12 = s2 * b.y, cyz = b.w;
            float t  = (fpx - u0) * idu;
            float hw = fmaf(fabsf(idu), 1.65f, 0.55f);
            int lo = max(0, __float2int_ru(t - hw));
            int hi = min(NX - 1, __float2int_rd(t + hw));
            for (int ix = lo; ix <= hi; ix++) {
                float X  = sX[ix];
                float u  = fmaf(Fiz, fmaf(m0, X, cyz), cx);
                float dd = rintf(u) - fpx;
                if (fabsf(dd) > 1.5f) continue;
                float ddx = fpx - u;
                float j02 = (cx - u) * iz;
                float av  = fmaf(s2 * j02, j02, a0);
                float bv  = sj12 * j02;
                float det = fmaf(av, cS, -bv * bv);
                float e = K2 / det *
                    (fmaf(fmaf(cS, ddx, -2.0f * bv * ddy), ddx, av * ddy * ddy));
                float w = ex2f(e);
                const float* rec = pack + (size_t)(ix * NSL + sl) * PSTR;
                u64 w2;
                asm("mov.b64 %0, {%1, %1};" : "=l"(w2) : "f"(w));
                const ulonglong2* rf = reinterpret_cast<const ulonglong2*>(rec);
                ulonglong2 p0 = rf[0], p1 = rf[1], p2 = rf[2], p3 = rf[3];
                FMA2(acc[0], w2, p0.x, acc[0]);
                FMA2(acc[1], w2, p0.y, acc[1]);
                FMA2(acc[2], w2, p1.x, acc[2]);
                FMA2(acc[3], w2, p1.y, acc[3]);
                FMA2(acc[4], w2, p2.x, acc[4]);
                FMA2(acc[5], w2, p2.y, acc[5]);
                FMA2(acc[6], w2, p3.x, acc[6]);
                FMA2(acc[7], w2, p3.y, acc[7]);
                acc16 = fmaf(w, rec[16], acc16);
            }
        }
    }

    // ---- unpack + fused loss ----
    float l[NCH];
#pragma unroll
    for (int q = 0; q < 8; q++) {
        float lo, hi;
        asm("mov.b64 {%0, %1}, %2;" : "=f"(lo), "=f"(hi) : "l"(acc[q]));
        l[2 * q] = lo; l[2 * q + 1] = hi;
    }
    l[16] = acc16;

    float m = l[0];
#pragma unroll
    for (int c = 1; c < NCH; c++) m = fmaxf(m, l[c]);
    float s = 0.f;
#pragma unroll
    for (int c = 0; c < NCH; c++) s += __expf(l[c] - m);
    float lse = m + __logf(s);

    int g = gt[(size_t)cam * NPIX + (size_t)row * WW + px];
    float lg = l[0];
#pragma unroll
    for (int c = 1; c < NCH; c++) lg = (g == c) ? l[c] : lg;
    float wv = (g != 0) ? cw[g] : 0.0f;
    float accn = wv * (lse - lg);
    float accd = wv;

#pragma unroll
    for (int o = 16; o > 0; o >>= 1) {
        accn += __shfl_down_sync(0xFFFFFFFFu, accn, o);
        accd += __shfl_down_sync(0xFFFFFFFFu, accd, o);
    }
    if ((tid & 31) == 0) { wn[tid >> 5] = accn; wd[tid >> 5] = accd; }
    __syncthreads();
    if (tid == 0) {
        float an = 0.f, ad = 0.f;
#pragma unroll
        for (int q = 0; q < BTHR / 32; q++) { an += wn[q]; ad += wd[q]; }
        atomicAdd(&g_num[cam], (double)an);
        atomicAdd(&g_den[cam], (double)ad);
    }
}

// ---------------------------------------------------------------------------
// Fallback pipeline (structure check failed) — known-correct scatter path
// ---------------------------------------------------------------------------
__global__ void zero_fb_kernel() {
    if (g_flag) return;
    const size_t n4 = ((size_t)NCAM * NPIX * NCH) / 4;
    float4 z4 = make_float4(0.f, 0.f, 0.f, 0.f);
    float4* p = reinterpret_cast<float4*>(g_img);
    for (size_t i = (size_t)blockIdx.x * blockDim.x + threadIdx.x; i < n4;
         i += (size_t)gridDim.x * blockDim.x)
        p[i] = z4;
}

__global__ void __launch_bounds__(256)
splat_fb_kernel(const float* __restrict__ xyz, const float* __restrict__ feats,
                const float* __restrict__ opac, const float* __restrict__ vm,
                const float* __restrict__ Ks) {
    if (g_flag) return;
    int i = blockIdx.x * blockDim.x + threadIdx.x;
    if (i >= NPTS) return;
    const float X = xyz[3 * i], Y = xyz[3 * i + 1], Z = xyz[3 * i + 2];
    const float op = opac[i];
    float f[NCH];
#pragma unroll
    for (int c = 0; c < NCH; c++) f[c] = feats[(size_t)i * NCH + c];
    const float s2 = VOXS * VOXS;
#pragma unroll 1
    for (int cam = 0; cam < NCAM; cam++) {
        const float* M = vm + cam * 16;
        float p0 = M[0]*X + M[1]*Y + M[2]*Z + M[3];
        float p1 = M[4]*X + M[5]*Y + M[6]*Z + M[7];
        float p2 = M[8]*X + M[9]*Y + M[10]*Z + M[11];
        if (!(p2 > 0.1f)) continue;
        const float* K = Ks + cam * 9;
        const float fx = K[0], cx = K[2], fy = K[4], cy = K[5];
        float zc = fmaxf(p2, 0.001f), iz = 1.0f / zc;
        float u = fx * p0 * iz + cx, v = fy * p1 * iz + cy;
        float j00 = fx * iz, j11 = fy * iz;
        float j02 = -fx * p0 * iz * iz, j12 = -fy * p1 * iz * iz;
        float a = s2 * (j00*j00 + j02*j02) + 0.3f;
        float b = s2 * (j02*j12);
        float c = s2 * (j11*j11 + j12*j12) + 0.3f;
        float idet = 1.0f / (a*c - b*b);
        float ca = c*idet, cb = -b*idet, cc = a*idet;
        float ru = rintf(u), rv = rintf(v);
        if (ru < -1.f || ru > (float)WW || rv < -1.f || rv > (float)HH) continue;
#pragma unroll
        for (int ky = 0; ky < 3; ky++) {
            float py = rv + (float)(ky - 1);
            if (py < 0.f || py >= (float)HH) continue;
            float ddy = py - v;
#pragma unroll
            for (int kx = 0; kx < 3; kx++) {
                float pxf = ru + (float)(kx - 1);
                if (pxf < 0.f || pxf >= (float)WW) continue;
                float ddx = pxf - u;
                float e = -0.5f * (ca*ddx*ddx + 2.f*cb*ddx*ddy + cc*ddy*ddy);
                float w = op * __expf(e);
                float* base = g_img +
                    ((size_t)cam * NPIX + (size_t)((int)py * WW + (int)pxf)) * NCH;
#pragma unroll
                for (int ch = 0; ch < NCH; ch++) red_add_f32(base + ch, w * f[ch]);
            }
        }
    }
}

__global__ void __launch_bounds__(256)
loss_fb_kernel(const int* __restrict__ gt, const float* __restrict__ cw) {
    if (g_flag) return;
    int i = blockIdx.x * 256 + threadIdx.x;
    int cam = i / NPIX;
    const float* L = g_img + (size_t)i * NCH;
    float l[NCH];
#pragma unroll
    for (int c = 0; c < NCH; c++) l[c] = L[c];
    float m = l[0];
#pragma unroll
    for (int c = 1; c < NCH; c++) m = fmaxf(m, l[c]);
    float s = 0.f;
#pragma unroll
    for (int c = 0; c < NCH; c++) s += __expf(l[c] - m);
    float lse = m + __logf(s);
    int g = gt[i];
    float w = (g != 0) ? cw[g] : 0.0f;
    float num = w * (lse - L[g]);
    __shared__ float sn[256], sd[256];
    sn[threadIdx.x] = num; sd[threadIdx.x] = w;
    __syncthreads();
#pragma unroll
    for (int st = 128; st > 0; st >>= 1) {
        if (threadIdx.x < st) {
            sn[threadIdx.x] += sn[threadIdx.x + st];
            sd[threadIdx.x] += sd[threadIdx.x + st];
        }
        __syncthreads();
    }
    if (threadIdx.x == 0) {
        atomicAdd(&g_num[cam], (double)sn[0]);
        atomicAdd(&g_den[cam], (double)sd[0]);
    }
}

__global__ void finalize_kernel(float* out) {
    if (threadIdx.x == 0 && blockIdx.x == 0) {
        double acc = 0.0;
        for (int cam = 0; cam < NCAM; cam++) {
            double d = g_den[cam];
            if (d < 1e-8) d = 1e-8;
            acc += g_num[cam] / d;
        }
        out[0] = (float)(acc / (double)NCAM);
    }
}

// ---------------------------------------------------------------------------
extern "C" void kernel_launch(void* const* d_in, const int* in_sizes, int n_in,
                              void* d_out, int out_size) {
    const float* voxel_feats = (const float*)d_in[0];
    const float* density     = (const float*)d_in[1];
    const float* viewmats    = (const float*)d_in[2];
    const float* Ks          = (const float*)d_in[3];
    const int*   gt_sem      = (const int*)d_in[4];
    const float* pc_xyz      = (const float*)d_in[5];
    const float* cw          = (const float*)d_in[6];
    float* out = (float*)d_out;

    prep1_kernel<<<1, 32>>>(viewmats);                                   // #1
    prep2_kernel<<<(NSL + 255) / 256, 256>>>(pc_xyz, viewmats, Ks);      // #2
    verrepack_kernel<<<NPTS / 256, 256>>>(pc_xyz, voxel_feats, density); // #3
    fused_kernel<<<NCAM * (HH / BROWS) * NSEG, BTHR>>>(                  // #4 (profiled)
        pc_xyz, viewmats, Ks, gt_sem, cw);

    // fallback (no-op when g_flag == 1)
    zero_fb_kernel<<<1024, 256>>>();
    splat_fb_kernel<<<(NPTS + 255) / 256, 256>>>(pc_xyz, voxel_feats, density, viewmats, Ks);
    loss_fb_kernel<<<NCAM * NPIX / 256, 256>>>(gt_sem, cw);

    finalize_kernel<<<1, 1>>>(out);
}

// round 11
// speedup vs baseline: 1.0424x; 1.0424x over previous
#include <cuda_runtime.h>
#include <cstddef>
#include <cstdint>

#define NPTS   640000
#define NCAM   6
#define HH     512
#define WW     1408
#define NPIX   (HH * WW)
#define NCH    17
#define VOXS   0.4f
#define NX     200
#define NSL    3200               // scanlines; point idx = ix*NSL + sl
#define SEGW   128
#define NSEG   11                 // 11*128 == WW
#define BROWS  2
#define BTHR   256
#define LISTCAP 96
#define RECCAP 48
#define PSTR   20                 // packed record: 17 op-premult feats + op + 2 pad

typedef unsigned long long u64;

// Scratch: fast path = packed feats; fallback = logit image.
__device__ __align__(16) float g_img[(size_t)NCAM * NPIX * NCH];
__device__ double g_num[NCAM];
__device__ double g_den[NCAM];
__device__ int    g_flag;
__device__ float  g_rec0[NCAM][NSL][4];   // u0, inv_du, v, iz
__device__ float  g_rec1[NCAM][NSL][4];   // j00, j12, cS, c_yz
__device__ short  g_rv[NCAM][NSL];        // rint(v) or 32000

__device__ __forceinline__ void red_add_f32(float* addr, float a) {
    asm volatile("red.global.add.f32 [%0], %1;" :: "l"(addr), "f"(a) : "memory");
}
#define FMA2(d, a, b, c) \
    asm("fma.rn.f32x2 %0, %1, %2, %3;" : "=l"(d) : "l"(a), "l"(b), "l"(c))

__device__ __forceinline__ float ex2f(float x) {
    float r;
    asm("ex2.approx.ftz.f32 %0, %1;" : "=f"(r) : "f"(x));
    return r;
}

// ---------------------------------------------------------------------------
// 1) prep1: matrix structure check, zero accumulators
// ---------------------------------------------------------------------------
__global__ void prep1_kernel(const float* __restrict__ vm) {
    if (threadIdx.x == 0) {
        int ok = 1;
        for (int c = 0; c < NCAM; c++)
            if (vm[c * 16 + 4] != 0.0f || vm[c * 16 + 8] != 0.0f) ok = 0;
        g_flag = ok;
    }
    if (threadIdx.x < NCAM) { g_num[threadIdx.x] = 0.0; g_den[threadIdx.x] = 0.0; }
}

// ---------------------------------------------------------------------------
// 2) prep2: per (cam, scanline) records + |du| guard for single-probe loop
// ---------------------------------------------------------------------------
__global__ void __launch_bounds__(256)
prep2_kernel(const float* __restrict__ xyz, const float* __restrict__ vm,
             const float* __restrict__ Ks) {
    int sl = blockIdx.x * 256 + threadIdx.x;
    if (sl >= NSL) return;
    float X0 = xyz[3 * sl], Y0 = xyz[3 * sl + 1], Z0 = xyz[3 * sl + 2];
    float Xe = xyz[3 * ((size_t)(NX - 1) * NSL + sl)];
    for (int cam = 0; cam < NCAM; cam++) {
        const float* M = vm + cam * 16;
        const float* K = Ks + cam * 9;
        float m0  = M[0];
        float cyz = fmaf(M[1], Y0, fmaf(M[2], Z0, M[3]));
        float p1  = fmaf(M[4], X0, fmaf(M[5], Y0, fmaf(M[6],  Z0, M[7])));
        float p2  = fmaf(M[8], X0, fmaf(M[9], Y0, fmaf(M[10], Z0, M[11])));
        float fx = K[0], cx = K[2], fy = K[4], cy = K[5];
        float zc = fmaxf(p2, 0.001f), iz = 1.0f / zc;
        float v   = fy * p1 * iz + cy;
        float j00 = fx * iz, j11 = fy * iz;
        float j12 = -fy * p1 * iz * iz;
        float cS  = VOXS * VOXS * (j11 * j11 + j12 * j12) + 0.3f;
        float p00 = fmaf(m0, X0, cyz), p0e = fmaf(m0, Xe, cyz);
        float u0  = fx * p00 * iz + cx;
        float ue  = fx * p0e * iz + cx;
        float du  = (ue - u0) * (1.0f / (float)(NX - 1));
        bool  val = (p2 > 0.1f);
        float rvf = rintf(v);
        bool  rel = val && (rvf >= -1.5f) && (rvf <= (float)HH + 0.5f);
        // single-probe needs 2*hw < 1 with hw = 1.55*|idu| + 0.02
        //   => |idu| < 0.3097  => |du| > 3.23; guard at 3.3 for margin
        if (rel && fabsf(du) < 3.3f) atomicAnd(&g_flag, 0);
        float idu = (du != 0.0f) ? 1.0f / du : 0.0f;
        g_rec0[cam][sl][0] = u0;  g_rec0[cam][sl][1] = idu;
        g_rec0[cam][sl][2] = v;   g_rec0[cam][sl][3] = iz;
        g_rec1[cam][sl][0] = j00; g_rec1[cam][sl][1] = j12;
        g_rec1[cam][sl][2] = cS;  g_rec1[cam][sl][3] = cyz;
        g_rv[cam][sl] = rel ? (short)(int)rvf : (short)32000;
    }
}

// ---------------------------------------------------------------------------
// 3) verrepack: grid verification + coalesced repack of op-premultiplied feats
// ---------------------------------------------------------------------------
__global__ void __launch_bounds__(256)
verrepack_kernel(const float* __restrict__ xyz, const float* __restrict__ feats,
                 const float* __restrict__ opac) {
    __shared__ float sf[256 * NCH];
    const int blk = blockIdx.x;
    const int tid = threadIdx.x;
    const int i   = blk * 256 + tid;

    // structure verification: Y,Z scanline-const; X shared & linear in ix
    int ix = i / NSL, sl = i - ix * NSL;
    float X = xyz[3 * i], Y = xyz[3 * i + 1], Z = xyz[3 * i + 2];
    float X0 = xyz[0];
    float Xe = xyz[3 * (size_t)((NX - 1) * NSL)];
    float dX = (Xe - X0) * (1.0f / (float)(NX - 1));
    bool ok = (Y == xyz[3 * sl + 1]) && (Z == xyz[3 * sl + 2]) &&
              (X == xyz[3 * (size_t)(ix * NSL)]);
    float Xlin = fmaf((float)ix, dX, X0);
    ok = ok && (fabsf(X - Xlin) <= fmaf(0.01f, fabsf(dX), 1e-5f));
    if (!ok) atomicAnd(&g_flag, 0);

    // repack (coalesced read via smem), feats pre-multiplied by opacity
    const float* src = feats + (size_t)blk * 256 * NCH;
    for (int j = tid; j < 256 * NCH / 4; j += 256) {
        float4 vv = reinterpret_cast<const float4*>(src)[j];
        sf[4 * j] = vv.x; sf[4 * j + 1] = vv.y; sf[4 * j + 2] = vv.z; sf[4 * j + 3] = vv.w;
    }
    __syncthreads();
    float op = opac[i];
    float r[PSTR];
#pragma unroll
    for (int c = 0; c < NCH; c++) r[c] = op * sf[tid * NCH + c];
    r[17] = op; r[18] = 0.f; r[19] = 0.f;
    float4* o = reinterpret_cast<float4*>(g_img + (size_t)i * PSTR);
#pragma unroll
    for (int q = 0; q < 5; q++)
        o[q] = make_float4(r[4 * q], r[4 * q + 1], r[4 * q + 2], r[4 * q + 3]);
}

// ---------------------------------------------------------------------------
// 4) FUSED GATHER: block = 2 rows x 128 px. Per-row packed headers, SINGLE
//    probe per rel scanline (rint(t)), relevance bitmask in list, f32x2 acc.
// ---------------------------------------------------------------------------
__global__ void __launch_bounds__(BTHR)
fused_kernel(const float* __restrict__ xyz, const float* __restrict__ vm,
             const float* __restrict__ Ks, const int* __restrict__ gt,
             const float* __restrict__ cw) {
    if (!g_flag) return;
    const int bix = blockIdx.x;
    const int cam = bix / ((HH / BROWS) * NSEG);
    const int rem = bix - cam * ((HH / BROWS) * NSEG);
    const int rp  = rem / NSEG;
    const int seg = rem - rp * NSEG;
    const int r0  = rp * BROWS;
    const int tid = threadIdx.x;
    const int px  = seg * SEGW + (tid & (SEGW - 1));
    const int rowoff = tid >> 7;                 // 0 or 1
    const int row = r0 + rowoff;

    __shared__ float  sX[NX];
    __shared__ int    s_n;
    __shared__ int    Lsl[LISTCAP];              // sl | relmask<<16
    __shared__ int2   Lwin[LISTCAP];             // ilo, ihi
    __shared__ float4 LV[LISTCAP];               // u0, idu, v, hw  (hot)
    __shared__ float4 LSa[LISTCAP];              // Fiz, iz, cS, a0 (staging)
    __shared__ float2 LSb[LISTCAP];              // sj12, cyz       (staging)
    __shared__ float4 sH[2][RECCAP];             // per row: u, A, B, C
    __shared__ float4 sF[RECCAP * 5];            // premult feats
    __shared__ float  wn[BTHR / 32], wd[BTHR / 32];

    for (int ix = tid; ix < NX; ix += BTHR)
        sX[ix] = xyz[3 * (size_t)(ix * NSL)];
    if (tid == 0) s_n = 0;
    __syncthreads();

    // scanlines whose stamps touch rows [r0, r0+1]; per-row relevance bits:
    //   bit0: |r0     - rv| <= 1  (d in [-1,1])
    //   bit1: |r0 + 1 - rv| <= 1  (d in [-2,0])
    for (int sl = tid; sl < NSL; sl += BTHR) {
        int d = r0 - (int)g_rv[cam][sl];
        int mask = ((d >= -1 && d <= 1) ? 1 : 0) | ((d >= -2 && d <= 0) ? 2 : 0);
        if (mask) {
            int k = atomicAdd(&s_n, 1);
            if (k < LISTCAP) Lsl[k] = sl | (mask << 16);
        }
    }
    __syncthreads();
    const int  nl  = s_n;
    const bool big = (nl > LISTCAP);

    const float fx = Ks[cam * 9 + 0], cx = Ks[cam * 9 + 2];
    const float m0 = vm[cam * 16 + 0];
    const float s2 = VOXS * VOXS;
    const float K2 = -0.72134752f;               // -0.5 * log2(e)
    const float px0f = (float)(seg * SEGW);
    const float px1f = px0f + (float)(SEGW - 1);

    if (!big) {
        for (int k = tid; k < nl; k += BTHR) {
            int sl = Lsl[k] & 0xFFFF;
            float4 a = *reinterpret_cast<const float4*>(g_rec0[cam][sl]);
            float4 b = *reinterpret_cast<const float4*>(g_rec1[cam][sl]);
            float hw = fmaf(fabsf(a.y), 1.55f, 0.02f);   // single-probe bound
            LV[k]  = make_float4(a.x, a.y, a.z, hw);
            LSa[k] = make_float4(fx * a.w, a.w, b.z, fmaf(s2 * b.x, b.x, 0.3f));
            LSb[k] = make_float2(s2 * b.y, b.w);
            float t0 = (px0f - a.x) * a.y;
            float t1 = (px1f - a.x) * a.y;
            int ilo = max(0, __float2int_ru(fminf(t0, t1) - hw));
            int ihi = min(NX - 1, __float2int_rd(fmaxf(t0, t1) + hw));
            Lwin[k] = make_int2(ilo, ihi);
        }
    }
    __syncthreads();

    u64 acc[8];
    float acc16 = 0.f;
#pragma unroll
    for (int q = 0; q < 8; q++) acc[q] = 0ull;

    const float fpx  = (float)px;
    const float rowf = (float)row;
    const float* pack = g_img;
    const float4* pack4 = reinterpret_cast<const float4*>(g_img);
    const int relbit = 1 << (16 + rowoff);

    if (!big) {
        for (int k = 0; k < nl; k++) {
            const int2 win = Lwin[k];
            const int  cnt = win.y - win.x + 1;
            if (cnt <= 0) continue;               // block-uniform

            if (cnt <= RECCAP) {
                const int ls = Lsl[k];
                const int sl = ls & 0xFFFF;
                __syncthreads();                  // protect sF/sH reuse
                // stage feats (one float4 per thread; nq <= 240)
                {
                    int nq = cnt * 5;
                    if (tid < nq) {
                        int rr = tid / 5, j = tid - rr * 5;
                        int base4 = (win.x * NSL + sl) * 5;   // 32-bit
                        sF[tid] = pack4[base4 + rr * (NSL * 5) + j];
                    }
                }
                // per-record, per-row header precompute
                if (tid < cnt) {
                    float4 sa = LSa[k]; float2 sb = LSb[k];
                    float v  = LV[k].z;
                    float X  = sX[win.x + tid];
                    float u  = fmaf(sa.x, fmaf(m0, X, sb.y), cx);
                    float j02 = (cx - u) * sa.y;
                    float av  = fmaf(s2 * j02, j02, sa.w);
                    float bv  = sb.x * j02;
                    float det = fmaf(av, sa.z, -bv * bv);
                    float idet = 1.0f / det;
                    float A   = K2 * sa.z * idet;
                    float B2  = -2.0f * K2 * bv * idet;      // 2*K2*cb
                    float Cc  = K2 * av * idet;
                    float dy0 = (float)r0 - v;
                    float dy1 = dy0 + 1.0f;
                    sH[0][tid] = make_float4(u, A, B2 * dy0, Cc * dy0 * dy0);
                    sH[1][tid] = make_float4(u, A, B2 * dy1, Cc * dy1 * dy1);
                }
                __syncthreads();

                if (ls & relbit) {                // rel for my row (bit test)
                    const float4 wv4 = LV[k];
                    float t   = (fpx - wv4.x) * wv4.y;
                    float ixf = rintf(t);
                    // unique candidate: window width 2*hw < 1
                    if (fabsf(ixf - t) < wv4.w) {
                        int ix = (int)ixf;
                        if (ix >= win.x && ix <= win.y) {
                            int jj = ix - win.x;
                            float4 h = sH[rowoff][jj];
                            float dd = rintf(h.x) - fpx;
                            if (fabsf(dd) < 1.5f) {
                                float ddx = fpx - h.x;
                                float e = fmaf(fmaf(h.y, ddx, h.z), ddx, h.w);
                                float w = ex2f(e);
                                u64 w2;
                                asm("mov.b64 %0, {%1, %1};" : "=l"(w2) : "f"(w));
                                const ulonglong2* rf =
                                    reinterpret_cast<const ulonglong2*>(&sF[jj * 5]);
                                ulonglong2 p0 = rf[0], p1 = rf[1];
                                FMA2(acc[0], w2, p0.x, acc[0]);
                                FMA2(acc[1], w2, p0.y, acc[1]);
                                FMA2(acc[2], w2, p1.x, acc[2]);
                                FMA2(acc[3], w2, p1.y, acc[3]);
                                ulonglong2 p2 = rf[2], p3 = rf[3];
                                FMA2(acc[4], w2, p2.x, acc[4]);
                                FMA2(acc[5], w2, p2.y, acc[5]);
                                FMA2(acc[6], w2, p3.x, acc[6]);
                                FMA2(acc[7], w2, p3.y, acc[7]);
                                float4 f4 = sF[jj * 5 + 4];
                                acc16 = fmaf(w, f4.x, acc16);
                            }
                        }
                    }
                }
            } else {
                // defensive overflow: direct per-thread path, exact math
                const int ls = Lsl[k];
                if (!(ls & relbit)) continue;
                const int sl = ls & 0xFFFF;
                const float4 wv4 = LV[k];
                const float4 sa = LSa[k]; const float2 sb = LSb[k];
                const float ddy = rowf - wv4.z;
                float t = (fpx - wv4.x) * wv4.y;
                int clo = max(win.x, __float2int_ru(t - wv4.w));
                int chi = min(win.y, __float2int_rd(t + wv4.w));
                for (int ix = clo; ix <= chi; ix++) {
                    float X  = sX[ix];
                    float u  = fmaf(sa.x, fmaf(m0, X, sb.y), cx);
                    float dd = rintf(u) - fpx;
                    if (fabsf(dd) > 1.5f) continue;
                    float ddx = fpx - u;
                    float j02 = (cx - u) * sa.y;
                    float av  = fmaf(s2 * j02, j02, sa.w);
                    float bv  = sb.x * j02;
                    float det = fmaf(av, sa.z, -bv * bv);
                    float e = K2 / det *
                        (fmaf(fmaf(sa.z, ddx, -2.0f * bv * ddy), ddx, av * ddy * ddy));
                    float w = ex2f(e);
                    u64 w2;
                    asm("mov.b64 %0, {%1, %1};" : "=l"(w2) : "f"(w));
                    const ulonglong2* rf = reinterpret_cast<const ulonglong2*>(
                        pack + (size_t)(ix * NSL + sl) * PSTR);
                    ulonglong2 p0 = rf[0], p1 = rf[1], p2 = rf[2], p3 = rf[3];
                    FMA2(acc[0], w2, p0.x, acc[0]);
                    FMA2(acc[1], w2, p0.y, acc[1]);
                    FMA2(acc[2], w2, p1.x, acc[2]);
                    FMA2(acc[3], w2, p1.y, acc[3]);
                    FMA2(acc[4], w2, p2.x, acc[4]);
                    FMA2(acc[5], w2, p2.y, acc[5]);
                    FMA2(acc[6], w2, p3.x, acc[6]);
                    FMA2(acc[7], w2, p3.y, acc[7]);
                    acc16 = fmaf(w, pack[(size_t)(ix * NSL + sl) * PSTR + 16], acc16);
                }
            }
        }
    } else {
        // never-expected overflow: full scanline scan, direct loads
        for (int sl = 0; sl < NSL; sl++) {
            int d = r0 - (int)g_rv[cam][sl];
            if (d < -2 || d > 1) continue;
            float4 a = *reinterpret_cast<const float4*>(g_rec0[cam][sl]);
            float4 b = *reinterpret_cast<const float4*>(g_rec1[cam][sl]);
            float u0 = a.x, idu = a.y, v = a.z, iz = a.w;
            if (fabsf(rowf - rintf(v)) > 1.0f) continue;
            float ddy = rowf - v;
            float Fiz = fx * iz, cS = b.z;
            float a0 = fmaf(s2 * b.x, b.x, 0.3f);
            float sj12 = s2 * b.y, cyz = b.w;
            float t  = (fpx - u0) * idu;
            float hw = fmaf(fabsf(idu), 1.55f, 0.02f);
            int lo = max(0, __float2int_ru(t - hw));
            int hi = min(NX - 1, __float2int_rd(t + hw));
            for (int ix = lo; ix <= hi; ix++) {
                float X  = sX[ix];
                float u  = fmaf(Fiz, fmaf(m0, X, cyz), cx);
                float dd = rintf(u) - fpx;
                if (fabsf(dd) > 1.5f) continue;
                float ddx = fpx - u;
                float j02 = (cx - u) * iz;
                float av  = fmaf(s2 * j02, j02, a0);
                float bv  = sj12 * j02;
                float det = fmaf(av, cS, -bv * bv);
                float e = K2 / det *
                    (fmaf(fmaf(cS, ddx, -2.0f * bv * ddy), ddx, av * ddy * ddy));
                float w = ex2f(e);
                const float* rec = pack + (size_t)(ix * NSL + sl) * PSTR;
                u64 w2;
                asm("mov.b64 %0, {%1, %1};" : "=l"(w2) : "f"(w));
                const ulonglong2* rf = reinterpret_cast<const ulonglong2*>(rec);
                ulonglong2 p0 = rf[0], p1 = rf[1], p2 = rf[2], p3 = rf[3];
                FMA2(acc[0], w2, p0.x, acc[0]);
                FMA2(acc[1], w2, p0.y, acc[1]);
                FMA2(acc[2], w2, p1.x, acc[2]);
                FMA2(acc[3], w2, p1.y, acc[3]);
                FMA2(acc[4], w2, p2.x, acc[4]);
                FMA2(acc[5], w2, p2.y, acc[5]);
                FMA2(acc[6], w2, p3.x, acc[6]);
                FMA2(acc[7], w2, p3.y, acc[7]);
                acc16 = fmaf(w, rec[16], acc16);
            }
        }
    }

    // ---- unpack + fused loss ----
    float l[NCH];
#pragma unroll
    for (int q = 0; q < 8; q++) {
        float lo, hi;
        asm("mov.b64 {%0, %1}, %2;" : "=f"(lo), "=f"(hi) : "l"(acc[q]));
        l[2 * q] = lo; l[2 * q + 1] = hi;
    }
    l[16] = acc16;

    float m = l[0];
#pragma unroll
    for (int c = 1; c < NCH; c++) m = fmaxf(m, l[c]);
    float s = 0.f;
#pragma unroll
    for (int c = 0; c < NCH; c++) s += __expf(l[c] - m);
    float lse = m + __logf(s);

    int g = gt[(size_t)cam * NPIX + (size_t)row * WW + px];
    float lg = l[0];
#pragma unroll
    for (int c = 1; c < NCH; c++) lg = (g == c) ? l[c] : lg;
    float wv = (g != 0) ? cw[g] : 0.0f;
    float accn = wv * (lse - lg);
    float accd = wv;

#pragma unroll
    for (int o = 16; o > 0; o >>= 1) {
        accn += __shfl_down_sync(0xFFFFFFFFu, accn, o);
        accd += __shfl_down_sync(0xFFFFFFFFu, accd, o);
    }
    if ((tid & 31) == 0) { wn[tid >> 5] = accn; wd[tid >> 5] = accd; }
    __syncthreads();
    if (tid == 0) {
        float an = 0.f, ad = 0.f;
#pragma unroll
        for (int q = 0; q < BTHR / 32; q++) { an += wn[q]; ad += wd[q]; }
        atomicAdd(&g_num[cam], (double)an);
        atomicAdd(&g_den[cam], (double)ad);
    }
}

// ---------------------------------------------------------------------------
// Fallback pipeline (structure check failed) — known-correct scatter path
// ---------------------------------------------------------------------------
__global__ void zero_fb_kernel() {
    if (g_flag) return;
    const size_t n4 = ((size_t)NCAM * NPIX * NCH) / 4;
    float4 z4 = make_float4(0.f, 0.f, 0.f, 0.f);
    float4* p = reinterpret_cast<float4*>(g_img);
    for (size_t i = (size_t)blockIdx.x * blockDim.x + threadIdx.x; i < n4;
         i += (size_t)gridDim.x * blockDim.x)
        p[i] = z4;
}

__global__ void __launch_bounds__(256)
splat_fb_kernel(const float* __restrict__ xyz, const float* __restrict__ feats,
                const float* __restrict__ opac, const float* __restrict__ vm,
                const float* __restrict__ Ks) {
    if (g_flag) return;
    int i = blockIdx.x * blockDim.x + threadIdx.x;
    if (i >= NPTS) return;
    const float X = xyz[3 * i], Y = xyz[3 * i + 1], Z = xyz[3 * i + 2];
    const float op = opac[i];
    float f[NCH];
#pragma unroll
    for (int c = 0; c < NCH; c++) f[c] = feats[(size_t)i * NCH + c];
    const float s2 = VOXS * VOXS;
#pragma unroll 1
    for (int cam = 0; cam < NCAM; cam++) {
        const float* M = vm + cam * 16;
        float p0 = M[0]*X + M[1]*Y + M[2]*Z + M[3];
        float p1 = M[4]*X + M[5]*Y + M[6]*Z + M[7];
        float p2 = M[8]*X + M[9]*Y + M[10]*Z + M[11];
        if (!(p2 > 0.1f)) continue;
        const float* K = Ks + cam * 9;
        const float fx = K[0], cx = K[2], fy = K[4], cy = K[5];
        float zc = fmaxf(p2, 0.001f), iz = 1.0f / zc;
        float u = fx * p0 * iz + cx, v = fy * p1 * iz + cy;
        float j00 = fx * iz, j11 = fy * iz;
        float j02 = -fx * p0 * iz * iz, j12 = -fy * p1 * iz * iz;
        float a = s2 * (j00*j00 + j02*j02) + 0.3f;
        float b = s2 * (j02*j12);
        float c = s2 * (j11*j11 + j12*j12) + 0.3f;
        float idet = 1.0f / (a*c - b*b);
        float ca = c*idet, cb = -b*idet, cc = a*idet;
        float ru = rintf(u), rv = rintf(v);
        if (ru < -1.f || ru > (float)WW || rv < -1.f || rv > (float)HH) continue;
#pragma unroll
        for (int ky = 0; ky < 3; ky++) {
            float py = rv + (float)(ky - 1);
            if (py < 0.f || py >= (float)HH) continue;
            float ddy = py - v;
#pragma unroll
            for (int kx = 0; kx < 3; kx++) {
                float pxf = ru + (float)(kx - 1);
                if (pxf < 0.f || pxf >= (float)WW) continue;
                float ddx = pxf - u;
                float e = -0.5f * (ca*ddx*ddx + 2.f*cb*ddx*ddy + cc*ddy*ddy);
                float w = op * __expf(e);
                float* base = g_img +
                    ((size_t)cam * NPIX + (size_t)((int)py * WW + (int)pxf)) * NCH;
#pragma unroll
                for (int ch = 0; ch < NCH; ch++) red_add_f32(base + ch, w * f[ch]);
            }
        }
    }
}

__global__ void __launch_bounds__(256)
loss_fb_kernel(const int* __restrict__ gt, const float* __restrict__ cw) {
    if (g_flag) return;
    int i = blockIdx.x * 256 + threadIdx.x;
    int cam = i / NPIX;
    const float* L = g_img + (size_t)i * NCH;
    float l[NCH];
#pragma unroll
    for (int c = 0; c < NCH; c++) l[c] = L[c];
    float m = l[0];
#pragma unroll
    for (int c = 1; c < NCH; c++) m = fmaxf(m, l[c]);
    float s = 0.f;
#pragma unroll
    for (int c = 0; c < NCH; c++) s += __expf(l[c] - m);
    float lse = m + __logf(s);
    int g = gt[i];
    float w = (g != 0) ? cw[g] : 0.0f;
    float num = w * (lse - L[g]);
    __shared__ float sn[256], sd[256];
    sn[threadIdx.x] = num; sd[threadIdx.x] = w;
    __syncthreads();
#pragma unroll
    for (int st = 128; st > 0; st >>= 1) {
        if (threadIdx.x < st) {
            sn[threadIdx.x] += sn[threadIdx.x + st];
            sd[threadIdx.x] += sd[threadIdx.x + st];
        }
        __syncthreads();
    }
    if (threadIdx.x == 0) {
        atomicAdd(&g_num[cam], (double)sn[0]);
        atomicAdd(&g_den[cam], (double)sd[0]);
    }
}

__global__ void finalize_kernel(float* out) {
    if (threadIdx.x == 0 && blockIdx.x == 0) {
        double acc = 0.0;
        for (int cam = 0; cam < NCAM; cam++) {
            double d = g_den[cam];
            if (d < 1e-8) d = 1e-8;
            acc += g_num[cam] / d;
        }
        out[0] = (float)(acc / (double)NCAM);
    }
}

// ---------------------------------------------------------------------------
extern "C" void kernel_launch(void* const* d_in, const int* in_sizes, int n_in,
                              void* d_out, int out_size) {
    const float* voxel_feats = (const float*)d_in[0];
    const float* density     = (const float*)d_in[1];
    const float* viewmats    = (const float*)d_in[2];
    const float* Ks          = (const float*)d_in[3];
    const int*   gt_sem      = (const int*)d_in[4];
    const float* pc_xyz      = (const float*)d_in[5];
    const float* cw          = (const float*)d_in[6];
    float* out = (float*)d_out;

    prep1_kernel<<<1, 32>>>(viewmats);                                   // #1
    prep2_kernel<<<(NSL + 255) / 256, 256>>>(pc_xyz, viewmats, Ks);      // #2
    verrepack_kernel<<<NPTS / 256, 256>>>(pc_xyz, voxel_feats, density); // #3
    fused_kernel<<<NCAM * (HH / BROWS) * NSEG, BTHR>>>(                  // #4 (profiled)
        pc_xyz, viewmats, Ks, gt_sem, cw);

    // fallback (no-op when g_flag == 1)
    zero_fb_kernel<<<1024, 256>>>();
    splat_fb_kernel<<<(NPTS + 255) / 256, 256>>>(pc_xyz, voxel_feats, density, viewmats, Ks);
    loss_fb_kernel<<<NCAM * NPIX / 256, 256>>>(gt_sem, cw);

    finalize_kernel<<<1, 1>>>(out);
}

// round 12
// speedup vs baseline: 1.3679x; 1.3123x over previous
#include <cuda_runtime.h>
#include <cstddef>
#include <cstdint>

#define NPTS   640000
#define NCAM   6
#define HH     512
#define WW     1408
#define NPIX   (HH * WW)
#define NCH    17
#define VOXS   0.4f
#define NX     200
#define NSL    3200               // scanlines; input point idx = ix*NSL + sl
#define SEGW   128
#define NSEG   11                 // 11*128 == WW
#define BROWS  2
#define BTHR   256
#define LISTCAP 96
#define PSTR   20                 // packed record: 17 op-premult feats + op + 2 pad

typedef unsigned long long u64;

// Scratch: fast path = packed feats (TRANSPOSED: rec[sl*NX+ix]); fallback = logit image.
__device__ __align__(16) float g_img[(size_t)NCAM * NPIX * NCH];
__device__ double g_num[NCAM];
__device__ double g_den[NCAM];
__device__ int    g_flag;
__device__ float  g_rec0[NCAM][NSL][4];   // u0, inv_du, v, iz
__device__ float  g_rec1[NCAM][NSL][4];   // j00, j12, cS, c_yz
__device__ short  g_rv[NCAM][NSL];        // rint(v) or 32000

__device__ __forceinline__ void red_add_f32(float* addr, float a) {
    asm volatile("red.global.add.f32 [%0], %1;" :: "l"(addr), "f"(a) : "memory");
}
#define FMA2(d, a, b, c) \
    asm("fma.rn.f32x2 %0, %1, %2, %3;" : "=l"(d) : "l"(a), "l"(b), "l"(c))

__device__ __forceinline__ float ex2f(float x) {
    float r;
    asm("ex2.approx.ftz.f32 %0, %1;" : "=f"(r) : "f"(x));
    return r;
}
__device__ __forceinline__ float rcpf(float x) {
    float r;
    asm("rcp.approx.ftz.f32 %0, %1;" : "=f"(r) : "f"(x));
    return r;
}

// ---------------------------------------------------------------------------
// 1) prep1: matrix structure check, zero accumulators
// ---------------------------------------------------------------------------
__global__ void prep1_kernel(const float* __restrict__ vm) {
    if (threadIdx.x == 0) {
        int ok = 1;
        for (int c = 0; c < NCAM; c++)
            if (vm[c * 16 + 4] != 0.0f || vm[c * 16 + 8] != 0.0f) ok = 0;
        g_flag = ok;
    }
    if (threadIdx.x < NCAM) { g_num[threadIdx.x] = 0.0; g_den[threadIdx.x] = 0.0; }
}

// ---------------------------------------------------------------------------
// 2) prep2: per (cam, scanline) records + |du| guard for single-probe loop
// ---------------------------------------------------------------------------
__global__ void __launch_bounds__(256)
prep2_kernel(const float* __restrict__ xyz, const float* __restrict__ vm,
             const float* __restrict__ Ks) {
    int sl = blockIdx.x * 256 + threadIdx.x;
    if (sl >= NSL) return;
    float X0 = xyz[3 * sl], Y0 = xyz[3 * sl + 1], Z0 = xyz[3 * sl + 2];
    float Xe = xyz[3 * ((size_t)(NX - 1) * NSL + sl)];
    for (int cam = 0; cam < NCAM; cam++) {
        const float* M = vm + cam * 16;
        const float* K = Ks + cam * 9;
        float m0  = M[0];
        float cyz = fmaf(M[1], Y0, fmaf(M[2], Z0, M[3]));
        float p1  = fmaf(M[4], X0, fmaf(M[5], Y0, fmaf(M[6],  Z0, M[7])));
        float p2  = fmaf(M[8], X0, fmaf(M[9], Y0, fmaf(M[10], Z0, M[11])));
        float fx = K[0], cx = K[2], fy = K[4], cy = K[5];
        float zc = fmaxf(p2, 0.001f), iz = 1.0f / zc;
        float v   = fy * p1 * iz + cy;
        float j00 = fx * iz, j11 = fy * iz;
        float j12 = -fy * p1 * iz * iz;
        float cS  = VOXS * VOXS * (j11 * j11 + j12 * j12) + 0.3f;
        float p00 = fmaf(m0, X0, cyz), p0e = fmaf(m0, Xe, cyz);
        float u0  = fx * p00 * iz + cx;
        float ue  = fx * p0e * iz + cx;
        float du  = (ue - u0) * (1.0f / (float)(NX - 1));
        bool  val = (p2 > 0.1f);
        float rvf = rintf(v);
        bool  rel = val && (rvf >= -1.5f) && (rvf <= (float)HH + 0.5f);
        // single-probe needs 2*hw < 1 with hw = 1.55*|idu| + 0.02
        //   => |idu| < 0.3097  => |du| > 3.23; guard at 3.3 for margin
        if (rel && fabsf(du) < 3.3f) atomicAnd(&g_flag, 0);
        float idu = (du != 0.0f) ? 1.0f / du : 0.0f;
        g_rec0[cam][sl][0] = u0;  g_rec0[cam][sl][1] = idu;
        g_rec0[cam][sl][2] = v;   g_rec0[cam][sl][3] = iz;
        g_rec1[cam][sl][0] = j00; g_rec1[cam][sl][1] = j12;
        g_rec1[cam][sl][2] = cS;  g_rec1[cam][sl][3] = cyz;
        g_rv[cam][sl] = rel ? (short)(int)rvf : (short)32000;
    }
}

// ---------------------------------------------------------------------------
// 3) verrepack: grid verification + repack of op-premultiplied feats into
//    scanline-major records rec[sl*NX + ix] (contiguous per scanline).
// ---------------------------------------------------------------------------
__global__ void __launch_bounds__(256)
verrepack_kernel(const float* __restrict__ xyz, const float* __restrict__ feats,
                 const float* __restrict__ opac) {
    __shared__ float sf[256 * NCH];
    const int blk = blockIdx.x;
    const int tid = threadIdx.x;
    const int i   = blk * 256 + tid;

    // structure verification: Y,Z scanline-const; X shared & linear in ix
    int ix = i / NSL, sl = i - ix * NSL;
    float X = xyz[3 * i], Y = xyz[3 * i + 1], Z = xyz[3 * i + 2];
    float X0 = xyz[0];
    float Xe = xyz[3 * (size_t)((NX - 1) * NSL)];
    float dX = (Xe - X0) * (1.0f / (float)(NX - 1));
    bool ok = (Y == xyz[3 * sl + 1]) && (Z == xyz[3 * sl + 2]) &&
              (X == xyz[3 * (size_t)(ix * NSL)]);
    float Xlin = fmaf((float)ix, dX, X0);
    ok = ok && (fabsf(X - Xlin) <= fmaf(0.01f, fabsf(dX), 1e-5f));
    if (!ok) atomicAnd(&g_flag, 0);

    // repack (coalesced read via smem), feats pre-multiplied by opacity
    const float* src = feats + (size_t)blk * 256 * NCH;
    for (int j = tid; j < 256 * NCH / 4; j += 256) {
        float4 vv = reinterpret_cast<const float4*>(src)[j];
        sf[4 * j] = vv.x; sf[4 * j + 1] = vv.y; sf[4 * j + 2] = vv.z; sf[4 * j + 3] = vv.w;
    }
    __syncthreads();
    float op = opac[i];
    float r[PSTR];
#pragma unroll
    for (int c = 0; c < NCH; c++) r[c] = op * sf[tid * NCH + c];
    r[17] = op; r[18] = 0.f; r[19] = 0.f;
    // transposed destination: record index sl*NX + ix
    float4* o = reinterpret_cast<float4*>(g_img + ((size_t)sl * NX + ix) * PSTR);
#pragma unroll
    for (int q = 0; q < 5; q++)
        o[q] = make_float4(r[4 * q], r[4 * q + 1], r[4 * q + 2], r[4 * q + 3]);
}

// ---------------------------------------------------------------------------
// 4) FUSED GATHER: block = 2 rows x 128 px. No staging, no in-loop barriers:
//    single probe per rel scanline + direct L1/L2 record loads (scanline-major
//    layout => warp reads ~640 contiguous bytes). f32x2 accumulation.
// ---------------------------------------------------------------------------
__global__ void __launch_bounds__(BTHR)
fused_kernel(const float* __restrict__ xyz, const float* __restrict__ vm,
             const float* __restrict__ Ks, const int* __restrict__ gt,
             const float* __restrict__ cw) {
    if (!g_flag) return;
    const int bix = blockIdx.x;
    const int cam = bix / ((HH / BROWS) * NSEG);
    const int rem = bix - cam * ((HH / BROWS) * NSEG);
    const int rp  = rem / NSEG;
    const int seg = rem - rp * NSEG;
    const int r0  = rp * BROWS;
    const int tid = threadIdx.x;
    const int px  = seg * SEGW + (tid & (SEGW - 1));
    const int rowoff = tid >> 7;                 // 0 or 1
    const int row = r0 + rowoff;

    __shared__ float  sX[NX];
    __shared__ int    s_n;
    __shared__ int    Lsl[LISTCAP];              // sl | relmask<<16
    __shared__ float4 LV[LISTCAP];               // u0, idu, v, hw
    __shared__ float4 LSa[LISTCAP];              // Fiz, iz, cS, a0
    __shared__ float2 LSb[LISTCAP];              // sj12, cyz
    __shared__ float  wn[BTHR / 32], wd[BTHR / 32];

    for (int ix = tid; ix < NX; ix += BTHR)
        sX[ix] = xyz[3 * (size_t)(ix * NSL)];
    if (tid == 0) s_n = 0;
    __syncthreads();

    // scanlines whose stamps touch rows [r0, r0+1]; per-row relevance bits:
    //   bit0: |r0     - rv| <= 1  (d in [-1,1])
    //   bit1: |r0 + 1 - rv| <= 1  (d in [-2,0])
    for (int sl = tid; sl < NSL; sl += BTHR) {
        int d = r0 - (int)g_rv[cam][sl];
        int mask = ((d >= -1 && d <= 1) ? 1 : 0) | ((d >= -2 && d <= 0) ? 2 : 0);
        if (mask) {
            int k = atomicAdd(&s_n, 1);
            if (k < LISTCAP) Lsl[k] = sl | (mask << 16);
        }
    }
    __syncthreads();
    const int  nl  = s_n;
    const bool big = (nl > LISTCAP);

    const float fx = Ks[cam * 9 + 0], cx = Ks[cam * 9 + 2];
    const float m0 = vm[cam * 16 + 0];
    const float s2 = VOXS * VOXS;
    const float K2 = -0.72134752f;               // -0.5 * log2(e)

    if (!big) {
        for (int k = tid; k < nl; k += BTHR) {
            int sl = Lsl[k] & 0xFFFF;
            float4 a = *reinterpret_cast<const float4*>(g_rec0[cam][sl]);
            float4 b = *reinterpret_cast<const float4*>(g_rec1[cam][sl]);
            float hw = fmaf(fabsf(a.y), 1.55f, 0.02f);   // single-probe bound
            LV[k]  = make_float4(a.x, a.y, a.z, hw);
            LSa[k] = make_float4(fx * a.w, a.w, b.z, fmaf(s2 * b.x, b.x, 0.3f));
            LSb[k] = make_float2(s2 * b.y, b.w);
        }
    }
    __syncthreads();

    u64 acc[8];
    float acc16 = 0.f;
#pragma unroll
    for (int q = 0; q < 8; q++) acc[q] = 0ull;

    const float fpx  = (float)px;
    const float rowf = (float)row;
    const float4* pack4 = reinterpret_cast<const float4*>(g_img);
    const int relbit = 1 << (16 + rowoff);

    if (!big) {
        for (int k = 0; k < nl; k++) {
            const int ls = Lsl[k];
            if (!(ls & relbit)) continue;          // warp-uniform skip
            const float4 wv4 = LV[k];
            float t   = (fpx - wv4.x) * wv4.y;
            float ixf = rintf(t);
            if (fabsf(ixf - t) >= wv4.w) continue; // unique candidate (2hw < 1)
            int ix = (int)ixf;
            if ((unsigned)ix >= (unsigned)NX) continue;

            const float4 sa = LSa[k];
            const float2 sb = LSb[k];
            float X  = sX[ix];
            float u  = fmaf(sa.x, fmaf(m0, X, sb.y), cx);
            float dd = rintf(u) - fpx;
            if (fabsf(dd) > 1.5f) continue;        // exact stamp test

            float ddx = fpx - u;
            float ddy = rowf - wv4.z;
            float j02 = (cx - u) * sa.y;
            float av  = fmaf(s2 * j02, j02, sa.w);
            float bv  = sb.x * j02;
            float det = fmaf(av, sa.z, -bv * bv);
            float e = K2 * rcpf(det) *
                (fmaf(fmaf(sa.z, ddx, -2.0f * bv * ddy), ddx, av * ddy * ddy));
            float w = ex2f(e);
            u64 w2;
            asm("mov.b64 %0, {%1, %1};" : "=l"(w2) : "f"(w));

            const int sl = ls & 0xFFFF;
            const ulonglong2* rf = reinterpret_cast<const ulonglong2*>(
                pack4 + ((size_t)sl * NX + ix) * 5);
            ulonglong2 p0 = rf[0], p1 = rf[1];
            FMA2(acc[0], w2, p0.x, acc[0]);
            FMA2(acc[1], w2, p0.y, acc[1]);
            FMA2(acc[2], w2, p1.x, acc[2]);
            FMA2(acc[3], w2, p1.y, acc[3]);
            ulonglong2 p2 = rf[2], p3 = rf[3];
            FMA2(acc[4], w2, p2.x, acc[4]);
            FMA2(acc[5], w2, p2.y, acc[5]);
            FMA2(acc[6], w2, p3.x, acc[6]);
            FMA2(acc[7], w2, p3.y, acc[7]);
            float f16 = reinterpret_cast<const float*>(rf)[16];
            acc16 = fmaf(w, f16, acc16);
        }
    } else {
        // never-expected overflow: full scanline scan, windowed direct loads
        for (int sl = 0; sl < NSL; sl++) {
            int d = r0 - (int)g_rv[cam][sl];
            if (d < -2 || d > 1) continue;
            float4 a = *reinterpret_cast<const float4*>(g_rec0[cam][sl]);
            float4 b = *reinterpret_cast<const float4*>(g_rec1[cam][sl]);
            float u0 = a.x, idu = a.y, v = a.z, iz = a.w;
            if (fabsf(rowf - rintf(v)) > 1.0f) continue;
            float ddy = rowf - v;
            float Fiz = fx * iz, cS = b.z;
            float a0 = fmaf(s2 * b.x, b.x, 0.3f);
            float sj12 = s2 * b.y, cyz = b.w;
            float t  = (fpx - u0) * idu;
            float hw = fmaf(fabsf(idu), 1.55f, 0.02f);
            int lo = max(0, __float2int_ru(t - hw));
            int hi = min(NX - 1, __float2int_rd(t + hw));
            for (int ix = lo; ix <= hi; ix++) {
                float X  = sX[ix];
                float u  = fmaf(Fiz, fmaf(m0, X, cyz), cx);
                float dd = rintf(u) - fpx;
                if (fabsf(dd) > 1.5f) continue;
                float ddx = fpx - u;
                float j02 = (cx - u) * iz;
                float av  = fmaf(s2 * j02, j02, a0);
                float bv  = sj12 * j02;
                float det = fmaf(av, cS, -bv * bv);
                float e = K2 / det *
                    (fmaf(fmaf(cS, ddx, -2.0f * bv * ddy), ddx, av * ddy * ddy));
                float w = ex2f(e);
                const float* rec = g_img + ((size_t)sl * NX + ix) * PSTR;
                u64 w2;
                asm("mov.b64 %0, {%1, %1};" : "=l"(w2) : "f"(w));
                const ulonglong2* rf = reinterpret_cast<const ulonglong2*>(rec);
                ulonglong2 p0 = rf[0], p1 = rf[1], p2 = rf[2], p3 = rf[3];
                FMA2(acc[0], w2, p0.x, acc[0]);
                FMA2(acc[1], w2, p0.y, acc[1]);
                FMA2(acc[2], w2, p1.x, acc[2]);
                FMA2(acc[3], w2, p1.y, acc[3]);
                FMA2(acc[4], w2, p2.x, acc[4]);
                FMA2(acc[5], w2, p2.y, acc[5]);
                FMA2(acc[6], w2, p3.x, acc[6]);
                FMA2(acc[7], w2, p3.y, acc[7]);
                acc16 = fmaf(w, rec[16], acc16);
            }
        }
    }

    // ---- unpack + fused loss ----
    float l[NCH];
#pragma unroll
    for (int q = 0; q < 8; q++) {
        float lo, hi;
        asm("mov.b64 {%0, %1}, %2;" : "=f"(lo), "=f"(hi) : "l"(acc[q]));
        l[2 * q] = lo; l[2 * q + 1] = hi;
    }
    l[16] = acc16;

    float m = l[0];
#pragma unroll
    for (int c = 1; c < NCH; c++) m = fmaxf(m, l[c]);
    float s = 0.f;
#pragma unroll
    for (int c = 0; c < NCH; c++) s += __expf(l[c] - m);
    float lse = m + __logf(s);

    int g = gt[(size_t)cam * NPIX + (size_t)row * WW + px];
    float lg = l[0];
#pragma unroll
    for (int c = 1; c < NCH; c++) lg = (g == c) ? l[c] : lg;
    float wv = (g != 0) ? cw[g] : 0.0f;
    float accn = wv * (lse - lg);
    float accd = wv;

#pragma unroll
    for (int o = 16; o > 0; o >>= 1) {
        accn += __shfl_down_sync(0xFFFFFFFFu, accn, o);
        accd += __shfl_down_sync(0xFFFFFFFFu, accd, o);
    }
    if ((tid & 31) == 0) { wn[tid >> 5] = accn; wd[tid >> 5] = accd; }
    __syncthreads();
    if (tid == 0) {
        float an = 0.f, ad = 0.f;
#pragma unroll
        for (int q = 0; q < BTHR / 32; q++) { an += wn[q]; ad += wd[q]; }
        atomicAdd(&g_num[cam], (double)an);
        atomicAdd(&g_den[cam], (double)ad);
    }
}

// ---------------------------------------------------------------------------
// Fallback pipeline (structure check failed) — known-correct scatter path
// ---------------------------------------------------------------------------
__global__ void zero_fb_kernel() {
    if (g_flag) return;
    const size_t n4 = ((size_t)NCAM * NPIX * NCH) / 4;
    float4 z4 = make_float4(0.f, 0.f, 0.f, 0.f);
    float4* p = reinterpret_cast<float4*>(g_img);
    for (size_t i = (size_t)blockIdx.x * blockDim.x + threadIdx.x; i < n4;
         i += (size_t)gridDim.x * blockDim.x)
        p[i] = z4;
}

__global__ void __launch_bounds__(256)
splat_fb_kernel(const float* __restrict__ xyz, const float* __restrict__ feats,
                const float* __restrict__ opac, const float* __restrict__ vm,
                const float* __restrict__ Ks) {
    if (g_flag) return;
    int i = blockIdx.x * blockDim.x + threadIdx.x;
    if (i >= NPTS) return;
    const float X = xyz[3 * i], Y = xyz[3 * i + 1], Z = xyz[3 * i + 2];
    const float op = opac[i];
    float f[NCH];
#pragma unroll
    for (int c = 0; c < NCH; c++) f[c] = feats[(size_t)i * NCH + c];
    const float s2 = VOXS * VOXS;
#pragma unroll 1
    for (int cam = 0; cam < NCAM; cam++) {
        const float* M = vm + cam * 16;
        float p0 = M[0]*X + M[1]*Y + M[2]*Z + M[3];
        float p1 = M[4]*X + M[5]*Y + M[6]*Z + M[7];
        float p2 = M[8]*X + M[9]*Y + M[10]*Z + M[11];
        if (!(p2 > 0.1f)) continue;
        const float* K = Ks + cam * 9;
        const float fx = K[0], cx = K[2], fy = K[4], cy = K[5];
        float zc = fmaxf(p2, 0.001f), iz = 1.0f / zc;
        float u = fx * p0 * iz + cx, v = fy * p1 * iz + cy;
        float j00 = fx * iz, j11 = fy * iz;
        float j02 = -fx * p0 * iz * iz, j12 = -fy * p1 * iz * iz;
        float a = s2 * (j00*j00 + j02*j02) + 0.3f;
        float b = s2 * (j02*j12);
        float c = s2 * (j11*j11 + j12*j12) + 0.3f;
        float idet = 1.0f / (a*c - b*b);
        float ca = c*idet, cb = -b*idet, cc = a*idet;
        float ru = rintf(u), rv = rintf(v);
        if (ru < -1.f || ru > (float)WW || rv < -1.f || rv > (float)HH) continue;
#pragma unroll
        for (int ky = 0; ky < 3; ky++) {
            float py = rv + (float)(ky - 1);
            if (py < 0.f || py >= (float)HH) continue;
            float ddy = py - v;
#pragma unroll
            for (int kx = 0; kx < 3; kx++) {
                float pxf = ru + (float)(kx - 1);
                if (pxf < 0.f || pxf >= (float)WW) continue;
                float ddx = pxf - u;
                float e = -0.5f * (ca*ddx*ddx + 2.f*cb*ddx*ddy + cc*ddy*ddy);
                float w = op * __expf(e);
                float* base = g_img +
                    ((size_t)cam * NPIX + (size_t)((int)py * WW + (int)pxf)) * NCH;
#pragma unroll
                for (int ch = 0; ch < NCH; ch++) red_add_f32(base + ch, w * f[ch]);
            }
        }
    }
}

__global__ void __launch_bounds__(256)
loss_fb_kernel(const int* __restrict__ gt, const float* __restrict__ cw) {
    if (g_flag) return;
    int i = blockIdx.x * 256 + threadIdx.x;
    int cam = i / NPIX;
    const float* L = g_img + (size_t)i * NCH;
    float l[NCH];
#pragma unroll
    for (int c = 0; c < NCH; c++) l[c] = L[c];
    float m = l[0];
#pragma unroll
    for (int c = 1; c < NCH; c++) m = fmaxf(m, l[c]);
    float s = 0.f;
#pragma unroll
    for (int c = 0; c < NCH; c++) s += __expf(l[c] - m);
    float lse = m + __logf(s);
    int g = gt[i];
    float w = (g != 0) ? cw[g] : 0.0f;
    float num = w * (lse - L[g]);
    __shared__ float sn[256], sd[256];
    sn[threadIdx.x] = num; sd[threadIdx.x] = w;
    __syncthreads();
#pragma unroll
    for (int st = 128; st > 0; st >>= 1) {
        if (threadIdx.x < st) {
            sn[threadIdx.x] += sn[threadIdx.x + st];
            sd[threadIdx.x] += sd[threadIdx.x + st];
        }
        __syncthreads();
    }
    if (threadIdx.x == 0) {
        atomicAdd(&g_num[cam], (double)sn[0]);
        atomicAdd(&g_den[cam], (double)sd[0]);
    }
}

__global__ void finalize_kernel(float* out) {
    if (threadIdx.x == 0 && blockIdx.x == 0) {
        double acc = 0.0;
        for (int cam = 0; cam < NCAM; cam++) {
            double d = g_den[cam];
            if (d < 1e-8) d = 1e-8;
            acc += g_num[cam] / d;
        }
        out[0] = (float)(acc / (double)NCAM);
    }
}

// ---------------------------------------------------------------------------
extern "C" void kernel_launch(void* const* d_in, const int* in_sizes, int n_in,
                              void* d_out, int out_size) {
    const float* voxel_feats = (const float*)d_in[0];
    const float* density     = (const float*)d_in[1];
    const float* viewmats    = (const float*)d_in[2];
    const float* Ks          = (const float*)d_in[3];
    const int*   gt_sem      = (const int*)d_in[4];
    const float* pc_xyz      = (const float*)d_in[5];
    const float* cw          = (const float*)d_in[6];
    float* out = (float*)d_out;

    prep1_kernel<<<1, 32>>>(viewmats);                                   // #1
    prep2_kernel<<<(NSL + 255) / 256, 256>>>(pc_xyz, viewmats, Ks);      // #2
    verrepack_kernel<<<NPTS / 256, 256>>>(pc_xyz, voxel_feats, density); // #3
    fused_kernel<<<NCAM * (HH / BROWS) * NSEG, BTHR>>>(                  // #4 (profiled)
        pc_xyz, viewmats, Ks, gt_sem, cw);

    // fallback (no-op when g_flag == 1)
    zero_fb_kernel<<<1024, 256>>>();
    splat_fb_kernel<<<(NPTS + 255) / 256, 256>>>(pc_xyz, voxel_feats, density, viewmats, Ks);
    loss_fb_kernel<<<NCAM * NPIX / 256, 256>>>(gt_sem, cw);

    finalize_kernel<<<1, 1>>>(out);
}

// round 13
// speedup vs baseline: 1.6536x; 1.2089x over previous
#include <cuda_runtime.h>
#include <cstddef>
#include <cstdint>

#define NPTS   640000
#define NCAM   6
#define HH     512
#define WW     1408
#define NPIX   (HH * WW)
#define NCH    17
#define VOXS   0.4f
#define NX     200
#define NSL    3200               // scanlines; input point idx = ix*NSL + sl
#define SEGW   128
#define NSEG   11                 // 11*128 == WW
#define BROWS  2
#define BTHR   256
#define LCAP   48                 // per-(cam,row) list capacity
#define PSTR   20                 // packed record: 17 op-premult feats + op + 2 pad

typedef unsigned long long u64;

// Scratch: fast path = packed feats (TRANSPOSED: rec[sl*NX+ix]); fallback = logit image.
__device__ __align__(16) float g_img[(size_t)NCAM * NPIX * NCH];
__device__ double g_num[NCAM];
__device__ double g_den[NCAM];
__device__ int    g_flag;
__device__ float  g_rec0[NCAM][NSL][4];   // u0, inv_du, v, iz   (big/fallback path)
__device__ float  g_rec1[NCAM][NSL][4];   // j00, j12, cS, c_yz
__device__ short  g_rv[NCAM][NSL];        // rint(v) or 32000
__device__ int    g_lcnt[NCAM][HH];       // per-(cam,row) list counts
__device__ __align__(16) float4 g_lrec[NCAM][HH][LCAP * 3];  // 3 float4 per entry

__device__ __forceinline__ void red_add_f32(float* addr, float a) {
    asm volatile("red.global.add.f32 [%0], %1;" :: "l"(addr), "f"(a) : "memory");
}
#define FMA2(d, a, b, c) \
    asm("fma.rn.f32x2 %0, %1, %2, %3;" : "=l"(d) : "l"(a), "l"(b), "l"(c))

__device__ __forceinline__ float ex2f(float x) {
    float r;
    asm("ex2.approx.ftz.f32 %0, %1;" : "=f"(r) : "f"(x));
    return r;
}
__device__ __forceinline__ float rcpf(float x) {
    float r;
    asm("rcp.approx.ftz.f32 %0, %1;" : "=f"(r) : "f"(x));
    return r;
}

// ---------------------------------------------------------------------------
// 1) prep1: matrix structure check, zero accumulators + list counters
// ---------------------------------------------------------------------------
__global__ void prep1_kernel(const float* __restrict__ vm) {
    int t = blockIdx.x * blockDim.x + threadIdx.x;
    if (t == 0) {
        int ok = 1;
        for (int c = 0; c < NCAM; c++)
            if (vm[c * 16 + 4] != 0.0f || vm[c * 16 + 8] != 0.0f) ok = 0;
        g_flag = ok;
    }
    if (t < NCAM) { g_num[t] = 0.0; g_den[t] = 0.0; }
    if (t < NCAM * HH) reinterpret_cast<int*>(g_lcnt)[t] = 0;
}

// ---------------------------------------------------------------------------
// 2) prep2: per (cam, scanline) records, |du| guard, per-(cam,row) list build
// ---------------------------------------------------------------------------
__global__ void __launch_bounds__(256)
prep2_kernel(const float* __restrict__ xyz, const float* __restrict__ vm,
             const float* __restrict__ Ks) {
    int sl = blockIdx.x * 256 + threadIdx.x;
    if (sl >= NSL) return;
    float X0 = xyz[3 * sl], Y0 = xyz[3 * sl + 1], Z0 = xyz[3 * sl + 2];
    float Xe = xyz[3 * ((size_t)(NX - 1) * NSL + sl)];
    const float s2k = VOXS * VOXS;
    for (int cam = 0; cam < NCAM; cam++) {
        const float* M = vm + cam * 16;
        const float* K = Ks + cam * 9;
        float m0  = M[0];
        float cyz = fmaf(M[1], Y0, fmaf(M[2], Z0, M[3]));
        float p1  = fmaf(M[4], X0, fmaf(M[5], Y0, fmaf(M[6],  Z0, M[7])));
        float p2  = fmaf(M[8], X0, fmaf(M[9], Y0, fmaf(M[10], Z0, M[11])));
        float fx = K[0], cx = K[2], fy = K[4], cy = K[5];
        float zc = fmaxf(p2, 0.001f), iz = 1.0f / zc;
        float v   = fy * p1 * iz + cy;
        float j00 = fx * iz, j11 = fy * iz;
        float j12 = -fy * p1 * iz * iz;
        float cS  = s2k * (j11 * j11 + j12 * j12) + 0.3f;
        float p00 = fmaf(m0, X0, cyz), p0e = fmaf(m0, Xe, cyz);
        float u0  = fx * p00 * iz + cx;
        float ue  = fx * p0e * iz + cx;
        float du  = (ue - u0) * (1.0f / (float)(NX - 1));
        bool  val = (p2 > 0.1f);
        float rvf = rintf(v);
        bool  rel = val && (rvf >= -1.5f) && (rvf <= (float)HH + 0.5f);
        // single-probe needs 2*hw < 1 with hw = 1.55*|idu| + 0.02
        if (rel && fabsf(du) < 3.3f) atomicAnd(&g_flag, 0);
        float idu = (du != 0.0f) ? 1.0f / du : 0.0f;
        g_rec0[cam][sl][0] = u0;  g_rec0[cam][sl][1] = idu;
        g_rec0[cam][sl][2] = v;   g_rec0[cam][sl][3] = iz;
        g_rec1[cam][sl][0] = j00; g_rec1[cam][sl][1] = j12;
        g_rec1[cam][sl][2] = cS;  g_rec1[cam][sl][3] = cyz;
        g_rv[cam][sl] = rel ? (short)(int)rvf : (short)32000;

        if (rel) {
            float hw = fmaf(fabsf(idu), 1.55f, 0.02f);
            float4 e0 = make_float4(u0, idu, hw, v);
            float4 e1 = make_float4(fx * iz, cyz, iz, cS);
            float4 e2 = make_float4(fmaf(s2k * j00, j00, 0.3f), s2k * j12,
                                    __int_as_float(sl), 0.f);
            int rv = (int)rvf;
            int rlo = max(0, rv - 1), rhi = min(HH - 1, rv + 1);
            for (int r = rlo; r <= rhi; r++) {
                int c = atomicAdd(&g_lcnt[cam][r], 1);
                if (c < LCAP) {
                    g_lrec[cam][r][c * 3 + 0] = e0;
                    g_lrec[cam][r][c * 3 + 1] = e1;
                    g_lrec[cam][r][c * 3 + 2] = e2;
                }
            }
        }
    }
}

// ---------------------------------------------------------------------------
// 3) verrepack: grid verification + repack of op-premultiplied feats into
//    scanline-major records rec[sl*NX + ix] (contiguous per scanline).
// ---------------------------------------------------------------------------
__global__ void __launch_bounds__(256)
verrepack_kernel(const float* __restrict__ xyz, const float* __restrict__ feats,
                 const float* __restrict__ opac) {
    __shared__ float sf[256 * NCH];
    const int blk = blockIdx.x;
    const int tid = threadIdx.x;
    const int i   = blk * 256 + tid;

    // structure verification: Y,Z scanline-const; X shared & linear in ix
    int ix = i / NSL, sl = i - ix * NSL;
    float X = xyz[3 * i], Y = xyz[3 * i + 1], Z = xyz[3 * i + 2];
    float X0 = xyz[0];
    float Xe = xyz[3 * (size_t)((NX - 1) * NSL)];
    float dX = (Xe - X0) * (1.0f / (float)(NX - 1));
    bool ok = (Y == xyz[3 * sl + 1]) && (Z == xyz[3 * sl + 2]) &&
              (X == xyz[3 * (size_t)(ix * NSL)]);
    float Xlin = fmaf((float)ix, dX, X0);
    ok = ok && (fabsf(X - Xlin) <= fmaf(0.01f, fabsf(dX), 1e-5f));
    if (!ok) atomicAnd(&g_flag, 0);

    // repack (coalesced read via smem), feats pre-multiplied by opacity
    const float* src = feats + (size_t)blk * 256 * NCH;
    for (int j = tid; j < 256 * NCH / 4; j += 256) {
        float4 vv = reinterpret_cast<const float4*>(src)[j];
        sf[4 * j] = vv.x; sf[4 * j + 1] = vv.y; sf[4 * j + 2] = vv.z; sf[4 * j + 3] = vv.w;
    }
    __syncthreads();
    float op = opac[i];
    float r[PSTR];
#pragma unroll
    for (int c = 0; c < NCH; c++) r[c] = op * sf[tid * NCH + c];
    r[17] = op; r[18] = 0.f; r[19] = 0.f;
    float4* o = reinterpret_cast<float4*>(g_img + ((size_t)sl * NX + ix) * PSTR);
#pragma unroll
    for (int q = 0; q < 5; q++)
        o[q] = make_float4(r[4 * q], r[4 * q + 1], r[4 * q + 2], r[4 * q + 3]);
}

// ---------------------------------------------------------------------------
// 4) FUSED GATHER: block = 2 rows x 128 px. Precomputed per-(cam,row) lists
//    staged to SMEM once; each thread iterates only its row's entries.
//    Single probe + direct L1/L2 record loads. f32x2 accumulation.
// ---------------------------------------------------------------------------
__global__ void __launch_bounds__(BTHR)
fused_kernel(const float* __restrict__ xyz, const float* __restrict__ vm,
             const float* __restrict__ Ks, const int* __restrict__ gt,
             const float* __restrict__ cw) {
    if (!g_flag) return;
    const int bix = blockIdx.x;
    const int cam = bix / ((HH / BROWS) * NSEG);
    const int rem = bix - cam * ((HH / BROWS) * NSEG);
    const int rp  = rem / NSEG;
    const int seg = rem - rp * NSEG;
    const int r0  = rp * BROWS;
    const int tid = threadIdx.x;
    const int px  = seg * SEGW + (tid & (SEGW - 1));
    const int rowoff = tid >> 7;                 // 0 or 1
    const int row = r0 + rowoff;

    __shared__ float  sX[NX];
    __shared__ float4 sL[2][LCAP * 3];
    __shared__ float  wn[BTHR / 32], wd[BTHR / 32];

    for (int ix = tid; ix < NX; ix += BTHR)
        sX[ix] = xyz[3 * (size_t)(ix * NSL)];

    const int n = g_lcnt[cam][row];              // warp-uniform (row is)
    if (n <= LCAP) {
        const float4* flat = g_lrec[cam][row];
        const int th = tid & 127;
        for (int j = th; j < n * 3; j += 128)
            sL[rowoff][j] = flat[j];
    }
    __syncthreads();

    const float fx = Ks[cam * 9 + 0], cx = Ks[cam * 9 + 2];
    const float m0 = vm[cam * 16 + 0];
    const float s2 = VOXS * VOXS;
    const float K2 = -0.72134752f;               // -0.5 * log2(e)

    u64 acc[8];
    float acc16 = 0.f;
#pragma unroll
    for (int q = 0; q < 8; q++) acc[q] = 0ull;

    const float fpx  = (float)px;
    const float rowf = (float)row;
    const float4* pack4 = reinterpret_cast<const float4*>(g_img);

    if (n <= LCAP) {
        const float4* L = sL[rowoff];
        for (int k = 0; k < n; k++) {
            float4 e0 = L[k * 3];                // u0, idu, hw, v
            float t   = (fpx - e0.x) * e0.y;
            float ixf = rintf(t);
            if (fabsf(ixf - t) >= e0.z) continue;  // unique candidate (2hw<1)
            int ix = (int)ixf;
            if ((unsigned)ix >= (unsigned)NX) continue;

            float4 e1 = L[k * 3 + 1];            // Fiz, cyz, iz, cS
            float X  = sX[ix];
            float u  = fmaf(e1.x, fmaf(m0, X, e1.y), cx);
            float dd = rintf(u) - fpx;
            if (fabsf(dd) > 1.5f) continue;      // exact stamp test

            float4 e2 = L[k * 3 + 2];            // a0, sj12, slbits, -
            float ddx = fpx - u;
            float ddy = rowf - e0.w;
            float j02 = (cx - u) * e1.z;
            float av  = fmaf(s2 * j02, j02, e2.x);
            float bv  = e2.y * j02;
            float det = fmaf(av, e1.w, -bv * bv);
            float e = K2 * rcpf(det) *
                (fmaf(fmaf(e1.w, ddx, -2.0f * bv * ddy), ddx, av * ddy * ddy));
            float w = ex2f(e);
            u64 w2;
            asm("mov.b64 %0, {%1, %1};" : "=l"(w2) : "f"(w));

            const int sl = __float_as_int(e2.z);
            const ulonglong2* rf = reinterpret_cast<const ulonglong2*>(
                pack4 + ((size_t)sl * NX + ix) * 5);
            ulonglong2 p0 = rf[0], p1 = rf[1];
            FMA2(acc[0], w2, p0.x, acc[0]);
            FMA2(acc[1], w2, p0.y, acc[1]);
            FMA2(acc[2], w2, p1.x, acc[2]);
            FMA2(acc[3], w2, p1.y, acc[3]);
            ulonglong2 p2 = rf[2], p3 = rf[3];
            FMA2(acc[4], w2, p2.x, acc[4]);
            FMA2(acc[5], w2, p2.y, acc[5]);
            FMA2(acc[6], w2, p3.x, acc[6]);
            FMA2(acc[7], w2, p3.y, acc[7]);
            float f16 = reinterpret_cast<const float*>(rf)[16];
            acc16 = fmaf(w, f16, acc16);
        }
    } else {
        // overflow safety: full scanline scan, windowed direct loads (exact)
        for (int sl = 0; sl < NSL; sl++) {
            int d = row - (int)g_rv[cam][sl];
            if (d < -1 || d > 1) continue;
            float4 a = *reinterpret_cast<const float4*>(g_rec0[cam][sl]);
            float4 b = *reinterpret_cast<const float4*>(g_rec1[cam][sl]);
            float u0 = a.x, idu = a.y, v = a.z, iz = a.w;
            float ddy = rowf - v;
            float Fiz = fx * iz, cS = b.z;
            float a0 = fmaf(s2 * b.x, b.x, 0.3f);
            float sj12 = s2 * b.y, cyz = b.w;
            float t  = (fpx - u0) * idu;
            float hw = fmaf(fabsf(idu), 1.55f, 0.02f);
            int lo = max(0, __float2int_ru(t - hw));
            int hi = min(NX - 1, __float2int_rd(t + hw));
            for (int ix = lo; ix <= hi; ix++) {
                float X  = sX[ix];
                float u  = fmaf(Fiz, fmaf(m0, X, cyz), cx);
                float dd = rintf(u) - fpx;
                if (fabsf(dd) > 1.5f) continue;
                float ddx = fpx - u;
                float j02 = (cx - u) * iz;
                float av  = fmaf(s2 * j02, j02, a0);
                float bv  = sj12 * j02;
                float det = fmaf(av, cS, -bv * bv);
                float e = K2 / det *
                    (fmaf(fmaf(cS, ddx, -2.0f * bv * ddy), ddx, av * ddy * ddy));
                float w = ex2f(e);
                const float* rec = g_img + ((size_t)sl * NX + ix) * PSTR;
                u64 w2;
                asm("mov.b64 %0, {%1, %1};" : "=l"(w2) : "f"(w));
                const ulonglong2* rf = reinterpret_cast<const ulonglong2*>(rec);
                ulonglong2 p0 = rf[0], p1 = rf[1], p2 = rf[2], p3 = rf[3];
                FMA2(acc[0], w2, p0.x, acc[0]);
                FMA2(acc[1], w2, p0.y, acc[1]);
                FMA2(acc[2], w2, p1.x, acc[2]);
                FMA2(acc[3], w2, p1.y, acc[3]);
                FMA2(acc[4], w2, p2.x, acc[4]);
                FMA2(acc[5], w2, p2.y, acc[5]);
                FMA2(acc[6], w2, p3.x, acc[6]);
                FMA2(acc[7], w2, p3.y, acc[7]);
                acc16 = fmaf(w, rec[16], acc16);
            }
        }
    }

    // ---- unpack + fused loss ----
    float l[NCH];
#pragma unroll
    for (int q = 0; q < 8; q++) {
        float lo, hi;
        asm("mov.b64 {%0, %1}, %2;" : "=f"(lo), "=f"(hi) : "l"(acc[q]));
        l[2 * q] = lo; l[2 * q + 1] = hi;
    }
    l[16] = acc16;

    float m = l[0];
#pragma unroll
    for (int c = 1; c < NCH; c++) m = fmaxf(m, l[c]);
    float s = 0.f;
#pragma unroll
    for (int c = 0; c < NCH; c++) s += __expf(l[c] - m);
    float lse = m + __logf(s);

    int g = gt[(size_t)cam * NPIX + (size_t)row * WW + px];
    float lg = l[0];
#pragma unroll
    for (int c = 1; c < NCH; c++) lg = (g == c) ? l[c] : lg;
    float wv = (g != 0) ? cw[g] : 0.0f;
    float accn = wv * (lse - lg);
    float accd = wv;

#pragma unroll
    for (int o = 16; o > 0; o >>= 1) {
        accn += __shfl_down_sync(0xFFFFFFFFu, accn, o);
        accd += __shfl_down_sync(0xFFFFFFFFu, accd, o);
    }
    if ((tid & 31) == 0) { wn[tid >> 5] = accn; wd[tid >> 5] = accd; }
    __syncthreads();
    if (tid == 0) {
        float an = 0.f, ad = 0.f;
#pragma unroll
        for (int q = 0; q < BTHR / 32; q++) { an += wn[q]; ad += wd[q]; }
        atomicAdd(&g_num[cam], (double)an);
        atomicAdd(&g_den[cam], (double)ad);
    }
}

// ---------------------------------------------------------------------------
// Fallback pipeline (structure check failed) — known-correct scatter path
// ---------------------------------------------------------------------------
__global__ void zero_fb_kernel() {
    if (g_flag) return;
    const size_t n4 = ((size_t)NCAM * NPIX * NCH) / 4;
    float4 z4 = make_float4(0.f, 0.f, 0.f, 0.f);
    float4* p = reinterpret_cast<float4*>(g_img);
    for (size_t i = (size_t)blockIdx.x * blockDim.x + threadIdx.x; i < n4;
         i += (size_t)gridDim.x * blockDim.x)
        p[i] = z4;
}

__global__ void __launch_bounds__(256)
splat_fb_kernel(const float* __restrict__ xyz, const float* __restrict__ feats,
                const float* __restrict__ opac, const float* __restrict__ vm,
                const float* __restrict__ Ks) {
    if (g_flag) return;
    int i = blockIdx.x * blockDim.x + threadIdx.x;
    if (i >= NPTS) return;
    const float X = xyz[3 * i], Y = xyz[3 * i + 1], Z = xyz[3 * i + 2];
    const float op = opac[i];
    float f[NCH];
#pragma unroll
    for (int c = 0; c < NCH; c++) f[c] = feats[(size_t)i * NCH + c];
    const float s2 = VOXS * VOXS;
#pragma unroll 1
    for (int cam = 0; cam < NCAM; cam++) {
        const float* M = vm + cam * 16;
        float p0 = M[0]*X + M[1]*Y + M[2]*Z + M[3];
        float p1 = M[4]*X + M[5]*Y + M[6]*Z + M[7];
        float p2 = M[8]*X + M[9]*Y + M[10]*Z + M[11];
        if (!(p2 > 0.1f)) continue;
        const float* K = Ks + cam * 9;
        const float fx = K[0], cx = K[2], fy = K[4], cy = K[5];
        float zc = fmaxf(p2, 0.001f), iz = 1.0f / zc;
        float u = fx * p0 * iz + cx, v = fy * p1 * iz + cy;
        float j00 = fx * iz, j11 = fy * iz;
        float j02 = -fx * p0 * iz * iz, j12 = -fy * p1 * iz * iz;
        float a = s2 * (j00*j00 + j02*j02) + 0.3f;
        float b = s2 * (j02*j12);
        float c = s2 * (j11*j11 + j12*j12) + 0.3f;
        float idet = 1.0f / (a*c - b*b);
        float ca = c*idet, cb = -b*idet, cc = a*idet;
        float ru = rintf(u), rv = rintf(v);
        if (ru < -1.f || ru > (float)WW || rv < -1.f || rv > (float)HH) continue;
#pragma unroll
        for (int ky = 0; ky < 3; ky++) {
            float py = rv + (float)(ky - 1);
            if (py < 0.f || py >= (float)HH) continue;
            float ddy = py - v;
#pragma unroll
            for (int kx = 0; kx < 3; kx++) {
                float pxf = ru + (float)(kx - 1);
                if (pxf < 0.f || pxf >= (float)WW) continue;
                float ddx = pxf - u;
                float e = -0.5f * (ca*ddx*ddx + 2.f*cb*ddx*ddy + cc*ddy*ddy);
                float w = op * __expf(e);
                float* base = g_img +
                    ((size_t)cam * NPIX + (size_t)((int)py * WW + (int)pxf)) * NCH;
#pragma unroll
                for (int ch = 0; ch < NCH; ch++) red_add_f32(base + ch, w * f[ch]);
            }
        }
    }
}

__global__ void __launch_bounds__(256)
loss_fb_kernel(const int* __restrict__ gt, const float* __restrict__ cw) {
    if (g_flag) return;
    int i = blockIdx.x * 256 + threadIdx.x;
    int cam = i / NPIX;
    const float* L = g_img + (size_t)i * NCH;
    float l[NCH];
#pragma unroll
    for (int c = 0; c < NCH; c++) l[c] = L[c];
    float m = l[0];
#pragma unroll
    for (int c = 1; c < NCH; c++) m = fmaxf(m, l[c]);
    float s = 0.f;
#pragma unroll
    for (int c = 0; c < NCH; c++) s += __expf(l[c] - m);
    float lse = m + __logf(s);
    int g = gt[i];
    float w = (g != 0) ? cw[g] : 0.0f;
    float num = w * (lse - L[g]);
    __shared__ float sn[256], sd[256];
    sn[threadIdx.x] = num; sd[threadIdx.x] = w;
    __syncthreads();
#pragma unroll
    for (int st = 128; st > 0; st >>= 1) {
        if (threadIdx.x < st) {
            sn[threadIdx.x] += sn[threadIdx.x + st];
            sd[threadIdx.x] += sd[threadIdx.x + st];
        }
        __syncthreads();
    }
    if (threadIdx.x == 0) {
        atomicAdd(&g_num[cam], (double)sn[0]);
        atomicAdd(&g_den[cam], (double)sd[0]);
    }
}

__global__ void finalize_kernel(float* out) {
    if (threadIdx.x == 0 && blockIdx.x == 0) {
        double acc = 0.0;
        for (int cam = 0; cam < NCAM; cam++) {
            double d = g_den[cam];
            if (d < 1e-8) d = 1e-8;
            acc += g_num[cam] / d;
        }
        out[0] = (float)(acc / (double)NCAM);
    }
}

// ---------------------------------------------------------------------------
extern "C" void kernel_launch(void* const* d_in, const int* in_sizes, int n_in,
                              void* d_out, int out_size) {
    const float* voxel_feats = (const float*)d_in[0];
    const float* density     = (const float*)d_in[1];
    const float* viewmats    = (const float*)d_in[2];
    const float* Ks          = (const float*)d_in[3];
    const int*   gt_sem      = (const int*)d_in[4];
    const float* pc_xyz      = (const float*)d_in[5];
    const float* cw          = (const float*)d_in[6];
    float* out = (float*)d_out;

    prep1_kernel<<<16, 256>>>(viewmats);                                 // #1
    prep2_kernel<<<(NSL + 255) / 256, 256>>>(pc_xyz, viewmats, Ks);      // #2
    verrepack_kernel<<<NPTS / 256, 256>>>(pc_xyz, voxel_feats, density); // #3
    fused_kernel<<<NCAM * (HH / BROWS) * NSEG, BTHR>>>(                  // #4 (profiled)
        pc_xyz, viewmats, Ks, gt_sem, cw);

    // fallback (no-op when g_flag == 1)
    zero_fb_kernel<<<1024, 256>>>();
    splat_fb_kernel<<<(NPTS + 255) / 256, 256>>>(pc_xyz, voxel_feats, density, viewmats, Ks);
    loss_fb_kernel<<<NCAM * NPIX / 256, 256>>>(gt_sem, cw);

    finalize_kernel<<<1, 1>>>(out);
}